// round 7
// baseline (speedup 1.0000x reference)
#include <cuda_runtime.h>
#include <math.h>

#define BB   256
#define NPIX 1089
#define MDIM 272
#define CC   32
#define PADS 36
#define CH_STRIDE (35*PADS)   /* 1260 floats per padded channel */
#define CONV_THREADS 512
#define NITEM 2376            /* 33 rows * 9 x-runs * 8 co-groups */

#define FLAG_ACT_IN 1
#define FLAG_FLIP   2
#define FLAG_ACTDER 4
#define FLAG_GNORM  8

typedef unsigned long long u64;

// ---------------- device state (static, no allocation) ----------------
__device__ float d_P[NPIX*NPIX];
__device__ float d_PhiTb[BB*NPIX];
__device__ float d_x[BB*NPIX];
__device__ float d_z[BB*NPIX];
__device__ float d_gphi[BB*NPIX];
__device__ float d_dotm[BB*NPIX];
__device__ float d_x1[BB*CC*NPIX];
__device__ float d_x2[BB*CC*NPIX];
__device__ float d_x3[BB*CC*NPIX];
__device__ float d_g [BB*CC*NPIX];
__device__ float d_bA[BB*CC*NPIX];
__device__ float d_ngrad[BB];
__device__ float d_gamma;

// ---------------- packed f32x2 helpers ----------------
__device__ __forceinline__ u64 pk2(float a, float b) {
    u64 r; asm("mov.b64 %0, {%1,%2};" : "=l"(r) : "f"(a), "f"(b)); return r;
}
__device__ __forceinline__ void fma2(u64& d, u64 a, u64 b) {
    asm("fma.rn.f32x2 %0, %1, %2, %3;" : "=l"(d) : "l"(a), "l"(b), "l"(d));
}
__device__ __forceinline__ float2 upk2(u64 v) {
    float2 f; asm("mov.b64 {%0,%1}, %2;" : "=f"(f.x), "=f"(f.y) : "l"(v)); return f;
}

// ---------------- activation (eq. 33), DELTA = 0.01 ----------------
__device__ __forceinline__ float actf(float v) {
    if (fabsf(v) > 0.01f) return fmaxf(v, 0.0f);
    return fmaf(v*v, 25.0f, fmaf(v, 0.5f, 0.0025f));
}
__device__ __forceinline__ float actdf(float v) {
    if (fabsf(v) > 0.01f) return v > 0.0f ? 1.0f : 0.0f;
    return fmaf(v, 50.0f, 0.5f);
}

// ---------------- GEMM: P = Phi^T Phi (64x64 tiles, 4x4 per thread) ----------------
__global__ void k_phitphi64(const float* __restrict__ Phi) {
    if (blockIdx.x == 0 && blockIdx.y == 0 && threadIdx.x == 0 && threadIdx.y == 0)
        d_gamma = 1.0f;
    __shared__ float As[16][68];
    __shared__ float Bs[16][68];
    int ib = blockIdx.y * 64, jb = blockIdx.x * 64;
    int tx = threadIdx.x, ty = threadIdx.y;
    int t = ty * 16 + tx;
    float acc[4][4];
    #pragma unroll
    for (int r = 0; r < 4; r++)
        #pragma unroll
        for (int c = 0; c < 4; c++) acc[r][c] = 0.f;

    for (int k0 = 0; k0 < MDIM; k0 += 16) {
        #pragma unroll
        for (int q = t; q < 1024; q += 256) {
            int kk = q / 64, r = q % 64;
            As[kk][r] = (ib + r < NPIX) ? Phi[(k0 + kk) * NPIX + ib + r] : 0.f;
            Bs[kk][r] = (jb + r < NPIX) ? Phi[(k0 + kk) * NPIX + jb + r] : 0.f;
        }
        __syncthreads();
        #pragma unroll
        for (int kk = 0; kk < 16; kk++) {
            float4 a4 = *(const float4*)&As[kk][ty * 4];
            float4 b4 = *(const float4*)&Bs[kk][tx * 4];
            float ar[4] = {a4.x, a4.y, a4.z, a4.w};
            float br[4] = {b4.x, b4.y, b4.z, b4.w};
            #pragma unroll
            for (int r = 0; r < 4; r++)
                #pragma unroll
                for (int c = 0; c < 4; c++)
                    acc[r][c] = fmaf(ar[r], br[c], acc[r][c]);
        }
        __syncthreads();
    }
    #pragma unroll
    for (int r = 0; r < 4; r++) {
        int i = ib + ty * 4 + r;
        if (i >= NPIX) continue;
        #pragma unroll
        for (int c = 0; c < 4; c++) {
            int j = jb + tx * 4 + c;
            if (j < NPIX) d_P[i * NPIX + j] = acc[r][c];
        }
    }
}

// ---------------- phase GEMM: dot = src @ P  (64x64, 4x4) ----------------
__global__ void k_gemmP(const float* __restrict__ src, float* __restrict__ dst,
                        const float* __restrict__ alphas, int phase, int mode) {
    __shared__ float As[16][68];
    __shared__ float Bs[16][68];
    int bb = blockIdx.y * 64, jb = blockIdx.x * 64;
    int tx = threadIdx.x, ty = threadIdx.y;
    int t = ty * 16 + tx;
    float acc[4][4];
    #pragma unroll
    for (int r = 0; r < 4; r++)
        #pragma unroll
        for (int c = 0; c < 4; c++) acc[r][c] = 0.f;

    for (int k0 = 0; k0 < NPIX; k0 += 16) {
        #pragma unroll
        for (int q = t; q < 1024; q += 256) {
            int r = q / 16, kk = q % 16;
            As[kk][r] = (k0 + kk < NPIX) ? src[(bb + r) * NPIX + k0 + kk] : 0.f;
        }
        #pragma unroll
        for (int q = t; q < 1024; q += 256) {
            int kk = q / 64, c = q % 64;
            Bs[kk][c] = (k0 + kk < NPIX && jb + c < NPIX) ? d_P[(k0 + kk) * NPIX + jb + c] : 0.f;
        }
        __syncthreads();
        #pragma unroll
        for (int kk = 0; kk < 16; kk++) {
            float4 a4 = *(const float4*)&As[kk][ty * 4];
            float4 b4 = *(const float4*)&Bs[kk][tx * 4];
            float ar[4] = {a4.x, a4.y, a4.z, a4.w};
            float br[4] = {b4.x, b4.y, b4.z, b4.w};
            #pragma unroll
            for (int r = 0; r < 4; r++)
                #pragma unroll
                for (int c = 0; c < 4; c++)
                    acc[r][c] = fmaf(ar[r], br[c], acc[r][c]);
        }
        __syncthreads();
    }
    float alpha = fabsf(alphas[phase]);
    #pragma unroll
    for (int r = 0; r < 4; r++) {
        int b = bb + ty * 4 + r;
        #pragma unroll
        for (int c = 0; c < 4; c++) {
            int j = jb + tx * 4 + c;
            if (j < NPIX) {
                float dot = acc[r][c];
                float ptb = d_PhiTb[b * NPIX + j];
                if (mode == 0)
                    dst[b * NPIX + j] = src[b * NPIX + j] + alpha * (ptb - dot);
                else
                    dst[b * NPIX + j] = dot - ptb;
            }
        }
    }
}

// ---------------- z step: z = x - |alpha|*dotm ----------------
__global__ void k_zstep(const float* __restrict__ x, float* __restrict__ z,
                        const float* __restrict__ alphas, int phase) {
    float alpha = fabsf(alphas[phase]);
    size_t base = (size_t)blockIdx.x * NPIX;
    for (int j = threadIdx.x; j < NPIX; j += blockDim.x)
        z[base + j] = x[base + j] - alpha * d_dotm[base + j];
}

// ---------------- fused setup GEMMs (blockIdx.z: 0 = PhiTb, 1 = x0) ----------------
__global__ void k_setupF(const float* __restrict__ Phix, const float* __restrict__ Phi,
                         const float* __restrict__ Qinit,
                         float* __restrict__ dPhiTb, float* __restrict__ dx) {
    __shared__ float As[32][33];
    __shared__ float Bs[32][33];
    int tmode = blockIdx.z;
    const float* Bsrc = tmode == 0 ? Phi : Qinit;
    float* dst = tmode == 0 ? dPhiTb : dx;
    int bb = blockIdx.y * 32, jb = blockIdx.x * 32;
    int tx = threadIdx.x, ty = threadIdx.y;
    int t = ty * 16 + tx;
    float acc00 = 0.f, acc01 = 0.f, acc10 = 0.f, acc11 = 0.f;
    for (int k0 = 0; k0 < MDIM; k0 += 32) {
        for (int q = t; q < 1024; q += 256) {
            int kk = q % 32, r = q / 32;
            As[kk][r] = (k0 + kk < MDIM) ? Phix[(bb + r) * MDIM + k0 + kk] : 0.f;
        }
        if (tmode == 0) {
            for (int q = t; q < 1024; q += 256) {
                int kk = q / 32, j = q % 32;
                Bs[kk][j] = (k0 + kk < MDIM && jb + j < NPIX) ? Bsrc[(k0 + kk) * NPIX + jb + j] : 0.f;
            }
        } else {
            for (int q = t; q < 1024; q += 256) {
                int kk = q % 32, j = q / 32;
                Bs[kk][j] = (k0 + kk < MDIM && jb + j < NPIX) ? Bsrc[(jb + j) * MDIM + k0 + kk] : 0.f;
            }
        }
        __syncthreads();
        #pragma unroll
        for (int kk = 0; kk < 32; kk++) {
            float a0 = As[kk][ty*2], a1 = As[kk][ty*2+1];
            float b0 = Bs[kk][tx*2], b1 = Bs[kk][tx*2+1];
            acc00 = fmaf(a0, b0, acc00); acc01 = fmaf(a0, b1, acc01);
            acc10 = fmaf(a1, b0, acc10); acc11 = fmaf(a1, b1, acc11);
        }
        __syncthreads();
    }
    int b0 = bb + ty*2, j0 = jb + tx*2;
    if (j0     < NPIX) dst[(b0  ) * NPIX + j0  ] = acc00;
    if (j0 + 1 < NPIX) dst[(b0  ) * NPIX + j0+1] = acc01;
    if (j0     < NPIX) dst[(b0+1) * NPIX + j0  ] = acc10;
    if (j0 + 1 < NPIX) dst[(b0+1) * NPIX + j0+1] = acc11;
}

// ---------------- heavy conv core: horizontal 4-pixel run x 4 output channels --------
// Patch per ci: 3 rows x (LDS.128 + LDS.64) = 6 vector loads (18 values);
// weights: 1 LDS.128 per tap (4 co). 72 FFMA2 per ci. FMA-pipe-bound.
__device__ __forceinline__ void conv_core_h4(const float* s_in, const float* s_w,
                                             float* __restrict__ outb,
                                             const float* __restrict__ preb,
                                             bool actder, int tid) {
    for (int it = tid; it < NITEM; it += CONV_THREADS) {
        int g  = it & 7;            // co group: 4 channels
        int r  = it >> 3;
        int xq = r % 9;
        int y  = r / 9;             // 0..32
        int x0 = xq * 4;            // 0,4,...,32 (last run: 1 valid pixel)
        int nval = 33 - x0; if (nval > 4) nval = 4;

        u64 acc[4][2];
        #pragma unroll
        for (int i = 0; i < 4; i++) { acc[i][0] = 0ull; acc[i][1] = 0ull; }

        for (int ci = 0; ci < CC; ci++) {
            // stored rows y..y+2, stored cols x0..x0+5 (aligned vector loads)
            const float* rowb = s_in + ci * CH_STRIDE + y * PADS + x0;
            u64 vp[3][6];
            #pragma unroll
            for (int rr = 0; rr < 3; rr++) {
                const float* rp = rowb + rr * PADS;
                float4 f4 = *(const float4*)rp;          // LDS.128
                float2 f2 = *(const float2*)(rp + 4);    // LDS.64
                vp[rr][0] = pk2(f4.x, f4.x);
                vp[rr][1] = pk2(f4.y, f4.y);
                vp[rr][2] = pk2(f4.z, f4.z);
                vp[rr][3] = pk2(f4.w, f4.w);
                vp[rr][4] = pk2(f2.x, f2.x);
                vp[rr][5] = pk2(f2.y, f2.y);
            }
            const float* wcib = s_w + ci * 9 * CC + g * 4;
            #pragma unroll
            for (int ky = 0; ky < 3; ky++) {
                #pragma unroll
                for (int kx = 0; kx < 3; kx++) {
                    int k = ky * 3 + kx;
                    ulonglong2 ww = *(const ulonglong2*)(wcib + k * CC); // LDS.128: 4 co
                    #pragma unroll
                    for (int px = 0; px < 4; px++) {
                        fma2(acc[px][0], vp[ky][px + kx], ww.x);
                        fma2(acc[px][1], vp[ky][px + kx], ww.y);
                    }
                }
            }
        }

        int cobase = g * 4;
        for (int px = 0; px < nval; px++) {
            int p = y * 33 + x0 + px;
            #pragma unroll
            for (int j = 0; j < 2; j++) {
                float2 a = upk2(acc[px][j]);
                int co0 = cobase + 2 * j;
                if (actder) {
                    a.x *= actdf(preb[co0 * NPIX + p]);
                    a.y *= actdf(preb[(co0 + 1) * NPIX + p]);
                }
                outb[co0 * NPIX + p]       = a.x;
                outb[(co0 + 1) * NPIX + p] = a.y;
            }
        }
    }
}

// stage weights into s_w with layout [ci][k][co] (optionally flipped/transposed)
__device__ __forceinline__ void stage_w(const float* __restrict__ w, float* s_w,
                                        bool flip, int tid) {
    for (int idx = tid; idx < CC * CC * 9; idx += CONV_THREADS) {
        int kx = idx % 3, ky = (idx / 3) % 3;
        int i = (idx / 9) % CC, o = idx / (9 * CC);
        float v = w[idx];
        int eci, eco, ek;
        if (flip) { eci = o; eco = i; ek = (2 - ky) * 3 + (2 - kx); }
        else      { eci = i; eco = o; ek = ky * 3 + kx; }
        s_w[(eci * 9 + ek) * CC + eco] = v;
    }
}

// ---------------- heavy 32->32 3x3 conv (fwd or transposed) ----------------
__global__ __launch_bounds__(CONV_THREADS, 1) void k_conv(
        const float* __restrict__ in, const float* __restrict__ w,
        float* __restrict__ out, const float* __restrict__ pre,
        const float* __restrict__ soft, int flags) {
    extern __shared__ float smem[];
    float* s_in = smem;                    // CC * CH_STRIDE
    float* s_w  = smem + CC * CH_STRIDE;   // [ci][k][co]
    int n = blockIdx.x, tid = threadIdx.x;

    // zero input tile (vectorized)
    for (int i = tid; i < CC * CH_STRIDE / 4; i += CONV_THREADS)
        ((float4*)s_in)[i] = make_float4(0.f, 0.f, 0.f, 0.f);
    stage_w(w, s_w, (flags & FLAG_FLIP) != 0, tid);
    __syncthreads();

    const float* inb = in + (size_t)n * CC * NPIX;
    bool act_in = (flags & FLAG_ACT_IN) != 0;
    for (int idx = tid; idx < CC * NPIX; idx += CONV_THREADS) {
        int ci = idx / NPIX, p = idx - ci * NPIX;
        int y = p / 33, x = p - y * 33;
        float v = inb[idx];
        if (act_in) v = actf(v);
        s_in[ci * CH_STRIDE + (y + 1) * PADS + (x + 1)] = v;
    }
    __syncthreads();

    if (flags & FLAG_GNORM) {
        float thr = soft[0] * d_gamma;
        float inv_thr = 1.0f / thr;
        for (int p = tid; p < NPIX; p += CONV_THREADS) {
            int y = p / 33, x = p - y * 33;
            int off = (y + 1) * PADS + (x + 1);
            float v[CC];
            float s = 0.f;
            #pragma unroll
            for (int c = 0; c < CC; c++) {
                v[c] = s_in[c * CH_STRIDE + off];
                s = fmaf(v[c], v[c], s);
            }
            float nrm = sqrtf(s);
            float f = (nrm > thr) ? (1.0f / fmaxf(nrm, 1e-12f)) : inv_thr;
            #pragma unroll
            for (int c = 0; c < CC; c++) s_in[c * CH_STRIDE + off] = v[c] * f;
        }
        __syncthreads();
    }

    conv_core_h4(s_in, s_w,
                 out + (size_t)n * CC * NPIX,
                 pre + (size_t)n * CC * NPIX,
                 (flags & FLAG_ACTDER) != 0, tid);
}

// ---------------- fused conv1 + conv2: z -> x1 (gmem) -> act -> conv2 -> x2 ----------
__global__ __launch_bounds__(CONV_THREADS, 1) void k_conv12(
        const float* __restrict__ z, const float* __restrict__ w1,
        const float* __restrict__ w2,
        float* __restrict__ x1out, float* __restrict__ x2out) {
    extern __shared__ float smem[];
    float* s_in = smem;                           // CC * CH_STRIDE (act(x1), padded)
    float* s_w  = s_in + CC * CH_STRIDE;          // CC*CC*9 (c2 weights)
    float* s_z  = s_w + CC * CC * 9;              // CH_STRIDE (padded z)
    float* s_w1 = s_z + CH_STRIDE;                // 9*CC  [k][co]
    int n = blockIdx.x, tid = threadIdx.x;

    for (int i = tid; i < CC * CH_STRIDE / 4; i += CONV_THREADS)
        ((float4*)s_in)[i] = make_float4(0.f, 0.f, 0.f, 0.f);
    for (int i = tid; i < CH_STRIDE; i += CONV_THREADS) s_z[i] = 0.f;
    stage_w(w2, s_w, false, tid);
    for (int idx = tid; idx < CC * 9; idx += CONV_THREADS) {
        int o = idx / 9, k = idx % 9;
        s_w1[k * CC + o] = w1[idx];
    }
    __syncthreads();

    const float* zb = z + (size_t)n * NPIX;
    for (int p = tid; p < NPIX; p += CONV_THREADS) {
        int y = p / 33, x = p - y * 33;
        s_z[(y + 1) * PADS + (x + 1)] = zb[p];
    }
    __syncthreads();

    // conv1: thread per pixel, all 32 output channels
    float* x1b = x1out + (size_t)n * CC * NPIX;
    for (int p = tid; p < NPIX; p += CONV_THREADS) {
        int y = p / 33, x = p - y * 33;
        const float* sp = s_z + y * PADS + x;
        float zv[9];
        zv[0]=sp[0]; zv[1]=sp[1]; zv[2]=sp[2];
        zv[3]=sp[PADS]; zv[4]=sp[PADS+1]; zv[5]=sp[PADS+2];
        zv[6]=sp[2*PADS]; zv[7]=sp[2*PADS+1]; zv[8]=sp[2*PADS+2];
        float acc[CC];
        #pragma unroll
        for (int co = 0; co < CC; co++) acc[co] = 0.f;
        #pragma unroll
        for (int k = 0; k < 9; k++) {
            #pragma unroll
            for (int c4 = 0; c4 < 8; c4++) {
                float4 wv = *(const float4*)(s_w1 + k * CC + c4 * 4);
                acc[c4*4+0] = fmaf(zv[k], wv.x, acc[c4*4+0]);
                acc[c4*4+1] = fmaf(zv[k], wv.y, acc[c4*4+1]);
                acc[c4*4+2] = fmaf(zv[k], wv.z, acc[c4*4+2]);
                acc[c4*4+3] = fmaf(zv[k], wv.w, acc[c4*4+3]);
            }
        }
        int off = (y + 1) * PADS + (x + 1);
        #pragma unroll
        for (int co = 0; co < CC; co++) {
            x1b[co * NPIX + p] = acc[co];
            s_in[co * CH_STRIDE + off] = actf(acc[co]);
        }
    }
    __syncthreads();

    conv_core_h4(s_in, s_w, x2out + (size_t)n * CC * NPIX,
                 x1out, false, tid);
}

// ---------------- convT1 (32 -> 1), fused with x/gphi update ----------------
__global__ __launch_bounds__(CONV_THREADS, 1) void k_convT1(
        const float* __restrict__ in, const float* __restrict__ w1,
        const float* __restrict__ z, float* __restrict__ x,
        const float* __restrict__ dotm, float* __restrict__ gphi,
        const float* __restrict__ alphas, const float* __restrict__ betas,
        int phase, int mode, float* __restrict__ out_extra) {
    extern __shared__ float smem[];
    float* s_in = smem;                 // CC * CH_STRIDE
    __shared__ float s_w[CC * 9];       // flipped [o][k]
    int n = blockIdx.x, tid = threadIdx.x;
    for (int i = tid; i < CC * CH_STRIDE / 4; i += CONV_THREADS)
        ((float4*)s_in)[i] = make_float4(0.f, 0.f, 0.f, 0.f);
    for (int idx = tid; idx < CC * 9; idx += CONV_THREADS) {
        int o = idx / 9, k = idx % 9;
        int ky = k / 3, kx = k % 3;
        s_w[o * 9 + (2 - ky) * 3 + (2 - kx)] = w1[idx];
    }
    __syncthreads();
    const float* inb = in + (size_t)n * CC * NPIX;
    for (int idx = tid; idx < CC * NPIX; idx += CONV_THREADS) {
        int ci = idx / NPIX, p = idx - ci * NPIX;
        int y = p / 33, x2 = p - y * 33;
        s_in[ci * CH_STRIDE + (y + 1) * PADS + (x2 + 1)] = inb[idx];
    }
    __syncthreads();

    float a = fabsf(alphas[phase]), b = fabsf(betas[phase]);
    float tau = a * b / (a + b);

    for (int p = tid; p < NPIX; p += CONV_THREADS) {
        int y = p / 33, xx = p - y * 33;
        float acc = 0.f;
        const float* sbase = s_in + y * PADS + xx;
        for (int o = 0; o < CC; o++) {
            const float* sp = sbase + o * CH_STRIDE;
            const float* wp = s_w + o * 9;
            #pragma unroll
            for (int k = 0; k < 9; k++)
                acc = fmaf(sp[(k / 3) * PADS + (k % 3)], wp[k], acc);
        }
        size_t off = (size_t)n * NPIX + p;
        if (mode == 0) {
            float nx = z[off] - tau * acc;
            x[off] = nx;
            if (out_extra) out_extra[off] = nx;
        } else {
            gphi[off] = dotm[off] + acc;
        }
    }
}

// ---------------- row norms + gamma update ----------------
__global__ void k_rownorm(const float* __restrict__ gphi) {
    __shared__ float red[256];
    int bidx = blockIdx.x;
    float s = 0.f;
    for (int j = threadIdx.x; j < NPIX; j += 256) {
        float v = gphi[(size_t)bidx * NPIX + j];
        s = fmaf(v, v, s);
    }
    red[threadIdx.x] = s;
    __syncthreads();
    for (int off = 128; off > 0; off >>= 1) {
        if (threadIdx.x < off) red[threadIdx.x] += red[threadIdx.x + off];
        __syncthreads();
    }
    if (threadIdx.x == 0) d_ngrad[bidx] = sqrtf(red[0]);
}

__global__ void k_gamma(const float* __restrict__ soft_thr) {
    __shared__ float red[256];
    red[threadIdx.x] = d_ngrad[threadIdx.x];
    __syncthreads();
    for (int off = 128; off > 0; off >>= 1) {
        if (threadIdx.x < off) red[threadIdx.x] += red[threadIdx.x + off];
        __syncthreads();
    }
    if (threadIdx.x == 0) {
        float mean = red[0] / (float)BB;
        float g = d_gamma;
        if (mean < 15000.0f * g * soft_thr[0]) g *= 0.9f;
        d_gamma = g;
    }
}

// ---------------- host orchestration ----------------
#define SMEM_CONV ((CC * CH_STRIDE + CC * CC * 9) * (int)sizeof(float))              /* 198144 */
#define SMEM_C12  ((CC * CH_STRIDE + CC * CC * 9 + CH_STRIDE + 9 * CC) * (int)sizeof(float)) /* 204336 */
#define SMEM_T1   ((CC * CH_STRIDE) * (int)sizeof(float))                            /* 161280 */

static void grad_r_chain(const float* src, const float* c1, const float* c2,
                         const float* c3, const float* c4, const float* soft,
                         float* px1, float* px2, float* px3, float* pg, float* pbA,
                         const float* pz, float* px, const float* pdotm, float* pgphi,
                         const float* alphas, const float* betas,
                         int phase, int mode, float* out_extra) {
    k_conv12<<<BB, CONV_THREADS, SMEM_C12>>>(src, c1, c2, px1, px2);
    k_conv<<<BB, CONV_THREADS, SMEM_CONV>>>(px2, c3, px3, px1, soft, FLAG_ACT_IN);
    k_conv<<<BB, CONV_THREADS, SMEM_CONV>>>(px3, c4, pg,  px1, soft, FLAG_ACT_IN);
    k_conv<<<BB, CONV_THREADS, SMEM_CONV>>>(pg,  c4, pbA, px3, soft, FLAG_FLIP | FLAG_ACTDER | FLAG_GNORM);
    k_conv<<<BB, CONV_THREADS, SMEM_CONV>>>(pbA, c3, pg,  px2, soft, FLAG_FLIP | FLAG_ACTDER);
    k_conv<<<BB, CONV_THREADS, SMEM_CONV>>>(pg,  c2, pbA, px1, soft, FLAG_FLIP | FLAG_ACTDER);
    k_convT1<<<BB, CONV_THREADS, SMEM_T1>>>(pbA, c1, pz, px, pdotm, pgphi,
                                            alphas, betas, phase, mode, out_extra);
}

extern "C" void kernel_launch(void* const* d_in, const int* in_sizes, int n_in,
                              void* d_out, int out_size) {
    (void)in_sizes; (void)n_in; (void)out_size;
    const float* Phix   = (const float*)d_in[0];
    const float* Phi    = (const float*)d_in[1];
    const float* Qinit  = (const float*)d_in[2];
    const float* soft   = (const float*)d_in[3];
    const float* alphas = (const float*)d_in[4];
    const float* betas  = (const float*)d_in[5];
    const float* c1     = (const float*)d_in[6];
    const float* c2     = (const float*)d_in[7];
    const float* c3     = (const float*)d_in[8];
    const float* c4     = (const float*)d_in[9];
    float* out = (float*)d_out;

    cudaFuncSetAttribute(k_conv,   cudaFuncAttributeMaxDynamicSharedMemorySize, SMEM_CONV);
    cudaFuncSetAttribute(k_conv12, cudaFuncAttributeMaxDynamicSharedMemorySize, SMEM_C12);
    cudaFuncSetAttribute(k_convT1, cudaFuncAttributeMaxDynamicSharedMemorySize, SMEM_T1);

    float *px, *pz, *pgphi, *pdotm, *px1, *px2, *px3, *pg, *pbA, *pPhiTb;
    cudaGetSymbolAddress((void**)&px,     d_x);
    cudaGetSymbolAddress((void**)&pz,     d_z);
    cudaGetSymbolAddress((void**)&pgphi,  d_gphi);
    cudaGetSymbolAddress((void**)&pdotm,  d_dotm);
    cudaGetSymbolAddress((void**)&px1,    d_x1);
    cudaGetSymbolAddress((void**)&px2,    d_x2);
    cudaGetSymbolAddress((void**)&px3,    d_x3);
    cudaGetSymbolAddress((void**)&pg,     d_g);
    cudaGetSymbolAddress((void**)&pbA,    d_bA);
    cudaGetSymbolAddress((void**)&pPhiTb, d_PhiTb);

    dim3 tb16(16, 16);
    k_phitphi64<<<dim3(18, 18), tb16>>>(Phi);                       // + gamma init
    k_setupF<<<dim3(35, 8, 2), tb16>>>(Phix, Phi, Qinit, pPhiTb, px);

    for (int p = 0; p < 3; p++) {
        if (p == 0)
            k_gemmP<<<dim3(18, 4), tb16>>>(px, pz, alphas, p, 0);
        else
            k_zstep<<<BB, 256>>>(px, pz, alphas, p);
        grad_r_chain(pz, c1, c2, c3, c4, soft, px1, px2, px3, pg, pbA,
                     pz, px, pdotm, pgphi, alphas, betas, p, 0,
                     (p == 2) ? out : nullptr);
        if (p < 2) {
            k_gemmP<<<dim3(18, 4), tb16>>>(px, pdotm, alphas, p, 1);
            grad_r_chain(px, c1, c2, c3, c4, soft, px1, px2, px3, pg, pbA,
                         pz, px, pdotm, pgphi, alphas, betas, p, 1, nullptr);
            k_rownorm<<<BB, 256>>>(pgphi);
            k_gamma<<<1, 256>>>(soft);
        }
    }
}

// round 8
// speedup vs baseline: 1.0201x; 1.0201x over previous
#include <cuda_runtime.h>
#include <math.h>

#define BB   256
#define NPIX 1089
#define MDIM 272
#define CC   32
#define PR   36               /* padded row stride (floats) */
#define PCH  (33*PR)          /* padded gmem channel stride = 1188 */
#define CH_STRIDE (35*PR)     /* smem channel stride = 1260 */
#define GUARD 8
#define CONV_THREADS 512
#define NITEM 2376            /* 33 rows * 9 x-runs * 8 co-groups */

#define FLAG_ACT_IN 1
#define FLAG_FLIP   2
#define FLAG_ACTDER 4
#define FLAG_GNORM  8

typedef unsigned long long u64;

// ---------------- device state (static, no allocation) ----------------
__device__ float d_P[NPIX*NPIX];
__device__ float d_PhiTb[BB*NPIX];
__device__ float d_x[BB*NPIX];
__device__ float d_z[BB*NPIX];
__device__ float d_gphi[BB*NPIX];
__device__ float d_dotm[BB*NPIX];
__device__ float d_x1[BB*CC*PCH];
__device__ float d_x2[BB*CC*PCH];
__device__ float d_x3[BB*CC*PCH];
__device__ float d_g [BB*CC*PCH];
__device__ float d_bA[BB*CC*PCH];
__device__ float d_ngrad[BB];
__device__ float d_gamma;

// ---------------- packed f32x2 helpers ----------------
__device__ __forceinline__ u64 pk2(float a, float b) {
    u64 r; asm("mov.b64 %0, {%1,%2};" : "=l"(r) : "f"(a), "f"(b)); return r;
}
__device__ __forceinline__ void fma2(u64& d, u64 a, u64 b) {
    asm("fma.rn.f32x2 %0, %1, %2, %3;" : "=l"(d) : "l"(a), "l"(b), "l"(d));
}
__device__ __forceinline__ float2 upk2(u64 v) {
    float2 f; asm("mov.b64 {%0,%1}, %2;" : "=f"(f.x), "=f"(f.y) : "l"(v)); return f;
}

// ---------------- activation (eq. 33), DELTA = 0.01 ----------------
__device__ __forceinline__ float actf(float v) {
    if (fabsf(v) > 0.01f) return fmaxf(v, 0.0f);
    return fmaf(v*v, 25.0f, fmaf(v, 0.5f, 0.0025f));
}
__device__ __forceinline__ float actdf(float v) {
    if (fabsf(v) > 0.01f) return v > 0.0f ? 1.0f : 0.0f;
    return fmaf(v, 50.0f, 0.5f);
}

// ---------------- GEMM: P = Phi^T Phi (64x64 tiles, 4x4 per thread) ----------------
__global__ void k_phitphi64(const float* __restrict__ Phi) {
    if (blockIdx.x == 0 && blockIdx.y == 0 && threadIdx.x == 0 && threadIdx.y == 0)
        d_gamma = 1.0f;
    __shared__ float As[16][68];
    __shared__ float Bs[16][68];
    int ib = blockIdx.y * 64, jb = blockIdx.x * 64;
    int tx = threadIdx.x, ty = threadIdx.y;
    int t = ty * 16 + tx;
    float acc[4][4];
    #pragma unroll
    for (int r = 0; r < 4; r++)
        #pragma unroll
        for (int c = 0; c < 4; c++) acc[r][c] = 0.f;

    for (int k0 = 0; k0 < MDIM; k0 += 16) {
        #pragma unroll
        for (int q = t; q < 1024; q += 256) {
            int kk = q / 64, r = q % 64;
            As[kk][r] = (ib + r < NPIX) ? Phi[(k0 + kk) * NPIX + ib + r] : 0.f;
            Bs[kk][r] = (jb + r < NPIX) ? Phi[(k0 + kk) * NPIX + jb + r] : 0.f;
        }
        __syncthreads();
        #pragma unroll
        for (int kk = 0; kk < 16; kk++) {
            float4 a4 = *(const float4*)&As[kk][ty * 4];
            float4 b4 = *(const float4*)&Bs[kk][tx * 4];
            float ar[4] = {a4.x, a4.y, a4.z, a4.w};
            float br[4] = {b4.x, b4.y, b4.z, b4.w};
            #pragma unroll
            for (int r = 0; r < 4; r++)
                #pragma unroll
                for (int c = 0; c < 4; c++)
                    acc[r][c] = fmaf(ar[r], br[c], acc[r][c]);
        }
        __syncthreads();
    }
    #pragma unroll
    for (int r = 0; r < 4; r++) {
        int i = ib + ty * 4 + r;
        if (i >= NPIX) continue;
        #pragma unroll
        for (int c = 0; c < 4; c++) {
            int j = jb + tx * 4 + c;
            if (j < NPIX) d_P[i * NPIX + j] = acc[r][c];
        }
    }
}

// ---------------- phase GEMM: dot = src @ P  (64x64, 4x4) ----------------
__global__ void k_gemmP(const float* __restrict__ src, float* __restrict__ dst,
                        const float* __restrict__ alphas, int phase, int mode) {
    __shared__ float As[16][68];
    __shared__ float Bs[16][68];
    int bb = blockIdx.y * 64, jb = blockIdx.x * 64;
    int tx = threadIdx.x, ty = threadIdx.y;
    int t = ty * 16 + tx;
    float acc[4][4];
    #pragma unroll
    for (int r = 0; r < 4; r++)
        #pragma unroll
        for (int c = 0; c < 4; c++) acc[r][c] = 0.f;

    for (int k0 = 0; k0 < NPIX; k0 += 16) {
        #pragma unroll
        for (int q = t; q < 1024; q += 256) {
            int r = q / 16, kk = q % 16;
            As[kk][r] = (k0 + kk < NPIX) ? src[(bb + r) * NPIX + k0 + kk] : 0.f;
        }
        #pragma unroll
        for (int q = t; q < 1024; q += 256) {
            int kk = q / 64, c = q % 64;
            Bs[kk][c] = (k0 + kk < NPIX && jb + c < NPIX) ? d_P[(k0 + kk) * NPIX + jb + c] : 0.f;
        }
        __syncthreads();
        #pragma unroll
        for (int kk = 0; kk < 16; kk++) {
            float4 a4 = *(const float4*)&As[kk][ty * 4];
            float4 b4 = *(const float4*)&Bs[kk][tx * 4];
            float ar[4] = {a4.x, a4.y, a4.z, a4.w};
            float br[4] = {b4.x, b4.y, b4.z, b4.w};
            #pragma unroll
            for (int r = 0; r < 4; r++)
                #pragma unroll
                for (int c = 0; c < 4; c++)
                    acc[r][c] = fmaf(ar[r], br[c], acc[r][c]);
        }
        __syncthreads();
    }
    float alpha = fabsf(alphas[phase]);
    #pragma unroll
    for (int r = 0; r < 4; r++) {
        int b = bb + ty * 4 + r;
        #pragma unroll
        for (int c = 0; c < 4; c++) {
            int j = jb + tx * 4 + c;
            if (j < NPIX) {
                float dot = acc[r][c];
                float ptb = d_PhiTb[b * NPIX + j];
                if (mode == 0)
                    dst[b * NPIX + j] = src[b * NPIX + j] + alpha * (ptb - dot);
                else
                    dst[b * NPIX + j] = dot - ptb;
            }
        }
    }
}

// ---------------- z step: z = x - |alpha|*dotm ----------------
__global__ void k_zstep(const float* __restrict__ x, float* __restrict__ z,
                        const float* __restrict__ alphas, int phase) {
    float alpha = fabsf(alphas[phase]);
    size_t base = (size_t)blockIdx.x * NPIX;
    for (int j = threadIdx.x; j < NPIX; j += blockDim.x)
        z[base + j] = x[base + j] - alpha * d_dotm[base + j];
}

// ---------------- fused setup GEMMs (blockIdx.z: 0 = PhiTb, 1 = x0) ----------------
__global__ void k_setupF(const float* __restrict__ Phix, const float* __restrict__ Phi,
                         const float* __restrict__ Qinit,
                         float* __restrict__ dPhiTb, float* __restrict__ dx) {
    __shared__ float As[32][33];
    __shared__ float Bs[32][33];
    int tmode = blockIdx.z;
    const float* Bsrc = tmode == 0 ? Phi : Qinit;
    float* dst = tmode == 0 ? dPhiTb : dx;
    int bb = blockIdx.y * 32, jb = blockIdx.x * 32;
    int tx = threadIdx.x, ty = threadIdx.y;
    int t = ty * 16 + tx;
    float acc00 = 0.f, acc01 = 0.f, acc10 = 0.f, acc11 = 0.f;
    for (int k0 = 0; k0 < MDIM; k0 += 32) {
        for (int q = t; q < 1024; q += 256) {
            int kk = q % 32, r = q / 32;
            As[kk][r] = (k0 + kk < MDIM) ? Phix[(bb + r) * MDIM + k0 + kk] : 0.f;
        }
        if (tmode == 0) {
            for (int q = t; q < 1024; q += 256) {
                int kk = q / 32, j = q % 32;
                Bs[kk][j] = (k0 + kk < MDIM && jb + j < NPIX) ? Bsrc[(k0 + kk) * NPIX + jb + j] : 0.f;
            }
        } else {
            for (int q = t; q < 1024; q += 256) {
                int kk = q % 32, j = q / 32;
                Bs[kk][j] = (k0 + kk < MDIM && jb + j < NPIX) ? Bsrc[(jb + j) * MDIM + k0 + kk] : 0.f;
            }
        }
        __syncthreads();
        #pragma unroll
        for (int kk = 0; kk < 32; kk++) {
            float a0 = As[kk][ty*2], a1 = As[kk][ty*2+1];
            float b0 = Bs[kk][tx*2], b1 = Bs[kk][tx*2+1];
            acc00 = fmaf(a0, b0, acc00); acc01 = fmaf(a0, b1, acc01);
            acc10 = fmaf(a1, b0, acc10); acc11 = fmaf(a1, b1, acc11);
        }
        __syncthreads();
    }
    int b0 = bb + ty*2, j0 = jb + tx*2;
    if (j0     < NPIX) dst[(b0  ) * NPIX + j0  ] = acc00;
    if (j0 + 1 < NPIX) dst[(b0  ) * NPIX + j0+1] = acc01;
    if (j0     < NPIX) dst[(b0+1) * NPIX + j0  ] = acc10;
    if (j0 + 1 < NPIX) dst[(b0+1) * NPIX + j0+1] = acc11;
}

// ---------------- zero smem halo: guard + rows 0,34 of each channel ----------------
__device__ __forceinline__ void zero_halo(float* smem_base, float* s_in, int tid) {
    float4 z4 = make_float4(0.f, 0.f, 0.f, 0.f);
    for (int i = tid; i < 578; i += CONV_THREADS) {
        if (i < 2) ((float4*)smem_base)[i] = z4;
        else {
            int j = i - 2, ci = j / 18, r = j % 18;
            int row = (r < 9) ? 0 : 34, c4 = r % 9;
            *(float4*)(s_in + ci * CH_STRIDE + row * PR + c4 * 4) = z4;
        }
    }
}

// ---------------- padded-gmem -> smem staging (float4, tail-zeroed) ----------------
__device__ __forceinline__ void stage_in(const float* __restrict__ in, float* s_in,
                                         bool act_in, int tid) {
    const float4* in4 = (const float4*)in;
    for (int i = tid; i < CC * 297; i += CONV_THREADS) {
        int ci = i / 297, rem = i % 297, y = rem / 9, c = rem % 9;
        float4 f = in4[i];
        if (act_in) { f.x = actf(f.x); f.y = actf(f.y); f.z = actf(f.z); f.w = actf(f.w); }
        if (c == 8) { f.y = 0.f; f.z = 0.f; f.w = 0.f; }   // cols 33-35 padding
        *(float4*)(s_in + ci * CH_STRIDE + (y + 1) * PR + c * 4) = f;
    }
}

// stage weights into s_w with layout [ci][k][co] (optionally flipped/transposed)
__device__ __forceinline__ void stage_w(const float* __restrict__ w, float* s_w,
                                        bool flip, int tid) {
    for (int idx = tid; idx < CC * CC * 9; idx += CONV_THREADS) {
        int kx = idx % 3, ky = (idx / 3) % 3;
        int i = (idx / 9) % CC, o = idx / (9 * CC);
        float v = w[idx];
        int eci, eco, ek;
        if (flip) { eci = o; eco = i; ek = (2 - ky) * 3 + (2 - kx); }
        else      { eci = i; eco = o; ek = ky * 3 + kx; }
        s_w[(eci * 9 + ek) * CC + eco] = v;
    }
}

// ---------------- heavy conv core: 4-pixel run x 4 co, fully vectorized I/O --------
__device__ __forceinline__ void conv_core_h4(const float* s_in, const float* s_w,
                                             float* __restrict__ outb,
                                             const float* __restrict__ preb,
                                             bool actder, int tid) {
    for (int it = tid; it < NITEM; it += CONV_THREADS) {
        int g  = it & 7;            // co group: 4 channels
        int r  = it >> 3;
        int xq = r % 9;
        int y  = r / 9;             // pixel row 0..32
        int x0 = xq * 4;

        u64 acc[4][2];
        #pragma unroll
        for (int i = 0; i < 4; i++) { acc[i][0] = 0ull; acc[i][1] = 0ull; }

        for (int ci = 0; ci < CC; ci++) {
            // stored rows y..y+2 = pixel rows y-1..y+1; cols x0-1..x0+4
            const float* rowb = s_in + ci * CH_STRIDE + y * PR + x0;
            u64 vp[3][6];
            #pragma unroll
            for (int rr = 0; rr < 3; rr++) {
                const float* rp = rowb + rr * PR;
                float2 fl = *(const float2*)(rp - 2);   // LDS.64 (use .y = col x0-1)
                float4 fm = *(const float4*)(rp);       // LDS.128 cols x0..x0+3
                float  fr = rp[4];                      // LDS.32  col  x0+4
                vp[rr][0] = pk2(fl.y, fl.y);
                vp[rr][1] = pk2(fm.x, fm.x);
                vp[rr][2] = pk2(fm.y, fm.y);
                vp[rr][3] = pk2(fm.z, fm.z);
                vp[rr][4] = pk2(fm.w, fm.w);
                vp[rr][5] = pk2(fr, fr);
            }
            const float* wcib = s_w + ci * 9 * CC + g * 4;
            #pragma unroll
            for (int ky = 0; ky < 3; ky++) {
                #pragma unroll
                for (int kx = 0; kx < 3; kx++) {
                    ulonglong2 ww = *(const ulonglong2*)(wcib + (ky * 3 + kx) * CC);
                    #pragma unroll
                    for (int px = 0; px < 4; px++) {
                        fma2(acc[px][0], vp[ky][px + kx], ww.x);
                        fma2(acc[px][1], vp[ky][px + kx], ww.y);
                    }
                }
            }
        }

        int cobase = g * 4;
        int obase = y * PR + x0;
        #pragma unroll
        for (int j = 0; j < 2; j++) {
            float2 a0 = upk2(acc[0][j]), a1 = upk2(acc[1][j]);
            float2 a2 = upk2(acc[2][j]), a3 = upk2(acc[3][j]);
            float4 fA = make_float4(a0.x, a1.x, a2.x, a3.x);
            float4 fB = make_float4(a0.y, a1.y, a2.y, a3.y);
            int coA = cobase + 2 * j, coB = coA + 1;
            if (actder) {
                float4 pA = *(const float4*)(preb + coA * PCH + obase);
                float4 pB = *(const float4*)(preb + coB * PCH + obase);
                fA.x *= actdf(pA.x); fA.y *= actdf(pA.y); fA.z *= actdf(pA.z); fA.w *= actdf(pA.w);
                fB.x *= actdf(pB.x); fB.y *= actdf(pB.y); fB.z *= actdf(pB.z); fB.w *= actdf(pB.w);
            }
            *(float4*)(outb + coA * PCH + obase) = fA;
            *(float4*)(outb + coB * PCH + obase) = fB;
        }
    }
}

// ---------------- heavy 32->32 3x3 conv (fwd or transposed) ----------------
__global__ __launch_bounds__(CONV_THREADS, 1) void k_conv(
        const float* __restrict__ in, const float* __restrict__ w,
        float* __restrict__ out, const float* __restrict__ pre,
        const float* __restrict__ soft, int flags) {
    extern __shared__ float smem[];
    float* s_in = smem + GUARD;                 // CC * CH_STRIDE, no left halo, guard behind
    float* s_w  = s_in + CC * CH_STRIDE;        // [ci][k][co]
    int n = blockIdx.x, tid = threadIdx.x;

    zero_halo(smem, s_in, tid);
    stage_w(w, s_w, (flags & FLAG_FLIP) != 0, tid);
    __syncthreads();
    stage_in(in + (size_t)n * CC * PCH, s_in, (flags & FLAG_ACT_IN) != 0, tid);
    __syncthreads();

    if (flags & FLAG_GNORM) {
        float thr = soft[0] * d_gamma;
        float inv_thr = 1.0f / thr;
        for (int p = tid; p < NPIX; p += CONV_THREADS) {
            int y = p / 33, x = p - y * 33;
            int off = (y + 1) * PR + x;
            float v[CC];
            float s = 0.f;
            #pragma unroll
            for (int c = 0; c < CC; c++) {
                v[c] = s_in[c * CH_STRIDE + off];
                s = fmaf(v[c], v[c], s);
            }
            float nrm = sqrtf(s);
            float f = (nrm > thr) ? (1.0f / fmaxf(nrm, 1e-12f)) : inv_thr;
            #pragma unroll
            for (int c = 0; c < CC; c++) s_in[c * CH_STRIDE + off] = v[c] * f;
        }
        __syncthreads();
    }

    conv_core_h4(s_in, s_w,
                 out + (size_t)n * CC * PCH,
                 pre + (size_t)n * CC * PCH,
                 (flags & FLAG_ACTDER) != 0, tid);
}

// ---------------- fused conv1 + conv2: z -> x1 (padded gmem) -> act -> conv2 -> x2 --
__global__ __launch_bounds__(CONV_THREADS, 1) void k_conv12(
        const float* __restrict__ z, const float* __restrict__ w1,
        const float* __restrict__ w2,
        float* __restrict__ x1out, float* __restrict__ x2out) {
    extern __shared__ float smem[];
    float* s_in = smem + GUARD;                 // CC * CH_STRIDE
    float* s_w  = s_in + CC * CH_STRIDE;        // CC*CC*9 (c2 weights)
    float* s_z  = s_w + CC * CC * 9;            // CH_STRIDE (padded z, halo layout)
    float* s_w1 = s_z + CH_STRIDE;              // 9*CC  [k][co]
    int n = blockIdx.x, tid = threadIdx.x;

    zero_halo(smem, s_in, tid);
    // zero cols 33-35 of rows 1..33 (conv1 writes only cols 0..32)
    for (int i = tid; i < CC * 33 * 3; i += CONV_THREADS) {
        int ci = i / 99, rem = i % 99;
        int row = rem / 3 + 1, col = 33 + rem % 3;
        s_in[ci * CH_STRIDE + row * PR + col] = 0.f;
    }
    for (int i = tid; i < CH_STRIDE / 4; i += CONV_THREADS)
        ((float4*)s_z)[i] = make_float4(0.f, 0.f, 0.f, 0.f);
    stage_w(w2, s_w, false, tid);
    for (int idx = tid; idx < CC * 9; idx += CONV_THREADS) {
        int o = idx / 9, k = idx % 9;
        s_w1[k * CC + o] = w1[idx];
    }
    __syncthreads();

    const float* zb = z + (size_t)n * NPIX;
    for (int p = tid; p < NPIX; p += CONV_THREADS) {
        int y = p / 33, x = p - y * 33;
        s_z[(y + 1) * PR + (x + 1)] = zb[p];
    }
    __syncthreads();

    // conv1: thread per pixel, all 32 output channels
    float* x1b = x1out + (size_t)n * CC * PCH;
    for (int p = tid; p < NPIX; p += CONV_THREADS) {
        int y = p / 33, x = p - y * 33;
        const float* sp = s_z + y * PR + x;
        float zv[9];
        zv[0]=sp[0]; zv[1]=sp[1]; zv[2]=sp[2];
        zv[3]=sp[PR]; zv[4]=sp[PR+1]; zv[5]=sp[PR+2];
        zv[6]=sp[2*PR]; zv[7]=sp[2*PR+1]; zv[8]=sp[2*PR+2];
        float acc[CC];
        #pragma unroll
        for (int co = 0; co < CC; co++) acc[co] = 0.f;
        #pragma unroll
        for (int k = 0; k < 9; k++) {
            #pragma unroll
            for (int c4 = 0; c4 < 8; c4++) {
                float4 wv = *(const float4*)(s_w1 + k * CC + c4 * 4);
                acc[c4*4+0] = fmaf(zv[k], wv.x, acc[c4*4+0]);
                acc[c4*4+1] = fmaf(zv[k], wv.y, acc[c4*4+1]);
                acc[c4*4+2] = fmaf(zv[k], wv.z, acc[c4*4+2]);
                acc[c4*4+3] = fmaf(zv[k], wv.w, acc[c4*4+3]);
            }
        }
        int off = (y + 1) * PR + x;
        int ob = y * PR + x;
        #pragma unroll
        for (int co = 0; co < CC; co++) {
            x1b[co * PCH + ob] = acc[co];
            s_in[co * CH_STRIDE + off] = actf(acc[co]);
        }
    }
    __syncthreads();

    conv_core_h4(s_in, s_w, x2out + (size_t)n * CC * PCH,
                 x1out, false, tid);
}

// ---------------- convT1 (32 -> 1), fused with x/gphi update ----------------
__global__ __launch_bounds__(CONV_THREADS, 1) void k_convT1(
        const float* __restrict__ in, const float* __restrict__ w1,
        const float* __restrict__ z, float* __restrict__ x,
        const float* __restrict__ dotm, float* __restrict__ gphi,
        const float* __restrict__ alphas, const float* __restrict__ betas,
        int phase, int mode, float* __restrict__ out_extra) {
    extern __shared__ float smem[];
    float* s_in = smem + GUARD;         // CC * CH_STRIDE (no left halo)
    __shared__ float s_w[CC * 9];       // flipped [o][k]
    int n = blockIdx.x, tid = threadIdx.x;

    zero_halo(smem, s_in, tid);
    for (int idx = tid; idx < CC * 9; idx += CONV_THREADS) {
        int o = idx / 9, k = idx % 9;
        int ky = k / 3, kx = k % 3;
        s_w[o * 9 + (2 - ky) * 3 + (2 - kx)] = w1[idx];
    }
    __syncthreads();
    stage_in(in + (size_t)n * CC * PCH, s_in, false, tid);
    __syncthreads();

    float a = fabsf(alphas[phase]), b = fabsf(betas[phase]);
    float tau = a * b / (a + b);

    for (int p = tid; p < NPIX; p += CONV_THREADS) {
        int y = p / 33, xx = p - y * 33;
        float acc = 0.f;
        const float* sbase = s_in + y * PR + xx;   // stored rows y..y+2, cols xx-1..xx+1
        for (int o = 0; o < CC; o++) {
            const float* sp = sbase + o * CH_STRIDE;
            const float* wp = s_w + o * 9;
            #pragma unroll
            for (int k = 0; k < 9; k++)
                acc = fmaf(sp[(k / 3) * PR + (k % 3) - 1], wp[k], acc);
        }
        size_t off = (size_t)n * NPIX + p;
        if (mode == 0) {
            float nx = z[off] - tau * acc;
            x[off] = nx;
            if (out_extra) out_extra[off] = nx;
        } else {
            gphi[off] = dotm[off] + acc;
        }
    }
}

// ---------------- row norms + gamma update ----------------
__global__ void k_rownorm(const float* __restrict__ gphi) {
    __shared__ float red[256];
    int bidx = blockIdx.x;
    float s = 0.f;
    for (int j = threadIdx.x; j < NPIX; j += 256) {
        float v = gphi[(size_t)bidx * NPIX + j];
        s = fmaf(v, v, s);
    }
    red[threadIdx.x] = s;
    __syncthreads();
    for (int off = 128; off > 0; off >>= 1) {
        if (threadIdx.x < off) red[threadIdx.x] += red[threadIdx.x + off];
        __syncthreads();
    }
    if (threadIdx.x == 0) d_ngrad[bidx] = sqrtf(red[0]);
}

__global__ void k_gamma(const float* __restrict__ soft_thr) {
    __shared__ float red[256];
    red[threadIdx.x] = d_ngrad[threadIdx.x];
    __syncthreads();
    for (int off = 128; off > 0; off >>= 1) {
        if (threadIdx.x < off) red[threadIdx.x] += red[threadIdx.x + off];
        __syncthreads();
    }
    if (threadIdx.x == 0) {
        float mean = red[0] / (float)BB;
        float g = d_gamma;
        if (mean < 15000.0f * g * soft_thr[0]) g *= 0.9f;
        d_gamma = g;
    }
}

// ---------------- host orchestration ----------------
#define SMEM_CONV ((GUARD + CC * CH_STRIDE + CC * CC * 9) * (int)sizeof(float))      /* 198176 */
#define SMEM_C12  ((GUARD + CC * CH_STRIDE + CC * CC * 9 + CH_STRIDE + 9 * CC) * (int)sizeof(float)) /* 204368 */
#define SMEM_T1   ((GUARD + CC * CH_STRIDE) * (int)sizeof(float))                    /* 161312 */

static void grad_r_chain(const float* src, const float* c1, const float* c2,
                         const float* c3, const float* c4, const float* soft,
                         float* px1, float* px2, float* px3, float* pg, float* pbA,
                         const float* pz, float* px, const float* pdotm, float* pgphi,
                         const float* alphas, const float* betas,
                         int phase, int mode, float* out_extra) {
    k_conv12<<<BB, CONV_THREADS, SMEM_C12>>>(src, c1, c2, px1, px2);
    k_conv<<<BB, CONV_THREADS, SMEM_CONV>>>(px2, c3, px3, px1, soft, FLAG_ACT_IN);
    k_conv<<<BB, CONV_THREADS, SMEM_CONV>>>(px3, c4, pg,  px1, soft, FLAG_ACT_IN);
    k_conv<<<BB, CONV_THREADS, SMEM_CONV>>>(pg,  c4, pbA, px3, soft, FLAG_FLIP | FLAG_ACTDER | FLAG_GNORM);
    k_conv<<<BB, CONV_THREADS, SMEM_CONV>>>(pbA, c3, pg,  px2, soft, FLAG_FLIP | FLAG_ACTDER);
    k_conv<<<BB, CONV_THREADS, SMEM_CONV>>>(pg,  c2, pbA, px1, soft, FLAG_FLIP | FLAG_ACTDER);
    k_convT1<<<BB, CONV_THREADS, SMEM_T1>>>(pbA, c1, pz, px, pdotm, pgphi,
                                            alphas, betas, phase, mode, out_extra);
}

extern "C" void kernel_launch(void* const* d_in, const int* in_sizes, int n_in,
                              void* d_out, int out_size) {
    (void)in_sizes; (void)n_in; (void)out_size;
    const float* Phix   = (const float*)d_in[0];
    const float* Phi    = (const float*)d_in[1];
    const float* Qinit  = (const float*)d_in[2];
    const float* soft   = (const float*)d_in[3];
    const float* alphas = (const float*)d_in[4];
    const float* betas  = (const float*)d_in[5];
    const float* c1     = (const float*)d_in[6];
    const float* c2     = (const float*)d_in[7];
    const float* c3     = (const float*)d_in[8];
    const float* c4     = (const float*)d_in[9];
    float* out = (float*)d_out;

    cudaFuncSetAttribute(k_conv,   cudaFuncAttributeMaxDynamicSharedMemorySize, SMEM_CONV);
    cudaFuncSetAttribute(k_conv12, cudaFuncAttributeMaxDynamicSharedMemorySize, SMEM_C12);
    cudaFuncSetAttribute(k_convT1, cudaFuncAttributeMaxDynamicSharedMemorySize, SMEM_T1);

    float *px, *pz, *pgphi, *pdotm, *px1, *px2, *px3, *pg, *pbA, *pPhiTb;
    cudaGetSymbolAddress((void**)&px,     d_x);
    cudaGetSymbolAddress((void**)&pz,     d_z);
    cudaGetSymbolAddress((void**)&pgphi,  d_gphi);
    cudaGetSymbolAddress((void**)&pdotm,  d_dotm);
    cudaGetSymbolAddress((void**)&px1,    d_x1);
    cudaGetSymbolAddress((void**)&px2,    d_x2);
    cudaGetSymbolAddress((void**)&px3,    d_x3);
    cudaGetSymbolAddress((void**)&pg,     d_g);
    cudaGetSymbolAddress((void**)&pbA,    d_bA);
    cudaGetSymbolAddress((void**)&pPhiTb, d_PhiTb);

    dim3 tb16(16, 16);
    k_phitphi64<<<dim3(18, 18), tb16>>>(Phi);                       // + gamma init
    k_setupF<<<dim3(35, 8, 2), tb16>>>(Phix, Phi, Qinit, pPhiTb, px);

    for (int p = 0; p < 3; p++) {
        if (p == 0)
            k_gemmP<<<dim3(18, 4), tb16>>>(px, pz, alphas, p, 0);
        else
            k_zstep<<<BB, 256>>>(px, pz, alphas, p);
        grad_r_chain(pz, c1, c2, c3, c4, soft, px1, px2, px3, pg, pbA,
                     pz, px, pdotm, pgphi, alphas, betas, p, 0,
                     (p == 2) ? out : nullptr);
        if (p < 2) {
            k_gemmP<<<dim3(18, 4), tb16>>>(px, pdotm, alphas, p, 1);
            grad_r_chain(px, c1, c2, c3, c4, soft, px1, px2, px3, pg, pbA,
                         pz, px, pdotm, pgphi, alphas, betas, p, 1, nullptr);
            k_rownorm<<<BB, 256>>>(pgphi);
            k_gamma<<<1, 256>>>(soft);
        }
    }
}

// round 10
// speedup vs baseline: 2.4209x; 2.3733x over previous
#include <cuda_runtime.h>
#include <cuda_bf16.h>
#include <math.h>
#include <cstdint>

#define BB   256
#define NPIX 1089
#define MDIM 272
#define CC   32

#define FLAG_ACT_IN 1
#define FLAG_FLIP   2
#define FLAG_ACTDER 4
#define FLAG_GNORM  8

// tensor-conv geometry
#define TC_THREADS 256
#define FRONT   40            /* zero rows before padded-pixel 0 */
#define SROWS   1360
#define ROWW    20            /* u32 per smem row (80B stride, conflict-free ldmatrix) */
#define NTILES  69            /* ceil(1089/16) pixel tiles */
#define KSTEPS  18            /* 9 taps * 32 ci / 16 */
#define WT_STRIDE 290         /* bf16 per Wt row (32 co rows) */

#define OFF_ROWS (CC * WT_STRIDE * 2)            /* 18560 */
#define SMEM_TC  (OFF_ROWS + SROWS * ROWW * 4)   /* 127360 */
#define SMEM_T1N (SROWS * 64)                    /* 87040 */

// ---------------- device state (static, no allocation) ----------------
__device__ float d_P[NPIX*NPIX];
__device__ float d_PhiTb[BB*NPIX];
__device__ float d_x[BB*NPIX];
__device__ float d_z[BB*NPIX];
__device__ float d_gphi[BB*NPIX];
__device__ float d_dotm[BB*NPIX];
// pixel-major bf16 tensors: [image][pixel][32ch] as 16 u32 per pixel
__device__ unsigned int d_x1[BB*NPIX*16];
__device__ unsigned int d_x2[BB*NPIX*16];
__device__ unsigned int d_x3[BB*NPIX*16];
__device__ unsigned int d_g [BB*NPIX*16];
__device__ unsigned int d_bA[BB*NPIX*16];
__device__ float d_ngrad[BB];
__device__ float d_gamma;

__device__ __forceinline__ uint32_t smem_to_u32(const void* p) {
    uint32_t a;
    asm("{ .reg .u64 t; cvta.to.shared.u64 t, %1; cvt.u32.u64 %0, t; }" : "=r"(a) : "l"(p));
    return a;
}

// ---------------- bf16 pack/unpack ----------------
__device__ __forceinline__ float2 bupk(unsigned int u) {
    __nv_bfloat162 t = *reinterpret_cast<__nv_bfloat162*>(&u);
    return __bfloat1622float2(t);
}
__device__ __forceinline__ unsigned int bpk(float a, float b) {
    __nv_bfloat162 t = __floats2bfloat162_rn(a, b);
    return *reinterpret_cast<unsigned int*>(&t);
}

// ---------------- activation (eq. 33), DELTA = 0.01 ----------------
__device__ __forceinline__ float actf(float v) {
    if (fabsf(v) > 0.01f) return fmaxf(v, 0.0f);
    return fmaf(v*v, 25.0f, fmaf(v, 0.5f, 0.0025f));
}
__device__ __forceinline__ float actdf(float v) {
    if (fabsf(v) > 0.01f) return v > 0.0f ? 1.0f : 0.0f;
    return fmaf(v, 50.0f, 0.5f);
}

// ---------------- GEMM: P = Phi^T Phi ----------------
__global__ void k_phitphi64(const float* __restrict__ Phi) {
    if (blockIdx.x == 0 && blockIdx.y == 0 && threadIdx.x == 0 && threadIdx.y == 0)
        d_gamma = 1.0f;
    __shared__ float As[16][68];
    __shared__ float Bs[16][68];
    int ib = blockIdx.y * 64, jb = blockIdx.x * 64;
    int tx = threadIdx.x, ty = threadIdx.y;
    int t = ty * 16 + tx;
    float acc[4][4];
    #pragma unroll
    for (int r = 0; r < 4; r++)
        #pragma unroll
        for (int c = 0; c < 4; c++) acc[r][c] = 0.f;
    for (int k0 = 0; k0 < MDIM; k0 += 16) {
        #pragma unroll
        for (int q = t; q < 1024; q += 256) {
            int kk = q / 64, r = q % 64;
            As[kk][r] = (ib + r < NPIX) ? Phi[(k0 + kk) * NPIX + ib + r] : 0.f;
            Bs[kk][r] = (jb + r < NPIX) ? Phi[(k0 + kk) * NPIX + jb + r] : 0.f;
        }
        __syncthreads();
        #pragma unroll
        for (int kk = 0; kk < 16; kk++) {
            float4 a4 = *(const float4*)&As[kk][ty * 4];
            float4 b4 = *(const float4*)&Bs[kk][tx * 4];
            float ar[4] = {a4.x, a4.y, a4.z, a4.w};
            float br[4] = {b4.x, b4.y, b4.z, b4.w};
            #pragma unroll
            for (int r = 0; r < 4; r++)
                #pragma unroll
                for (int c = 0; c < 4; c++)
                    acc[r][c] = fmaf(ar[r], br[c], acc[r][c]);
        }
        __syncthreads();
    }
    #pragma unroll
    for (int r = 0; r < 4; r++) {
        int i = ib + ty * 4 + r;
        if (i >= NPIX) continue;
        #pragma unroll
        for (int c = 0; c < 4; c++) {
            int j = jb + tx * 4 + c;
            if (j < NPIX) d_P[i * NPIX + j] = acc[r][c];
        }
    }
}

// ---------------- phase GEMM ----------------
__global__ void k_gemmP(const float* __restrict__ src, float* __restrict__ dst,
                        const float* __restrict__ alphas, int phase, int mode) {
    __shared__ float As[16][68];
    __shared__ float Bs[16][68];
    int bb = blockIdx.y * 64, jb = blockIdx.x * 64;
    int tx = threadIdx.x, ty = threadIdx.y;
    int t = ty * 16 + tx;
    float acc[4][4];
    #pragma unroll
    for (int r = 0; r < 4; r++)
        #pragma unroll
        for (int c = 0; c < 4; c++) acc[r][c] = 0.f;
    for (int k0 = 0; k0 < NPIX; k0 += 16) {
        #pragma unroll
        for (int q = t; q < 1024; q += 256) {
            int r = q / 16, kk = q % 16;
            As[kk][r] = (k0 + kk < NPIX) ? src[(bb + r) * NPIX + k0 + kk] : 0.f;
        }
        #pragma unroll
        for (int q = t; q < 1024; q += 256) {
            int kk = q / 64, c = q % 64;
            Bs[kk][c] = (k0 + kk < NPIX && jb + c < NPIX) ? d_P[(k0 + kk) * NPIX + jb + c] : 0.f;
        }
        __syncthreads();
        #pragma unroll
        for (int kk = 0; kk < 16; kk++) {
            float4 a4 = *(const float4*)&As[kk][ty * 4];
            float4 b4 = *(const float4*)&Bs[kk][tx * 4];
            float ar[4] = {a4.x, a4.y, a4.z, a4.w};
            float br[4] = {b4.x, b4.y, b4.z, b4.w};
            #pragma unroll
            for (int r = 0; r < 4; r++)
                #pragma unroll
                for (int c = 0; c < 4; c++)
                    acc[r][c] = fmaf(ar[r], br[c], acc[r][c]);
        }
        __syncthreads();
    }
    float alpha = fabsf(alphas[phase]);
    #pragma unroll
    for (int r = 0; r < 4; r++) {
        int b = bb + ty * 4 + r;
        #pragma unroll
        for (int c = 0; c < 4; c++) {
            int j = jb + tx * 4 + c;
            if (j < NPIX) {
                float dot = acc[r][c];
                float ptb = d_PhiTb[b * NPIX + j];
                if (mode == 0)
                    dst[b * NPIX + j] = src[b * NPIX + j] + alpha * (ptb - dot);
                else
                    dst[b * NPIX + j] = dot - ptb;
            }
        }
    }
}

__global__ void k_zstep(const float* __restrict__ x, float* __restrict__ z,
                        const float* __restrict__ alphas, int phase) {
    float alpha = fabsf(alphas[phase]);
    size_t base = (size_t)blockIdx.x * NPIX;
    for (int j = threadIdx.x; j < NPIX; j += blockDim.x)
        z[base + j] = x[base + j] - alpha * d_dotm[base + j];
}

__global__ void k_setupF(const float* __restrict__ Phix, const float* __restrict__ Phi,
                         const float* __restrict__ Qinit,
                         float* __restrict__ dPhiTb, float* __restrict__ dx) {
    __shared__ float As[32][33];
    __shared__ float Bs[32][33];
    int tmode = blockIdx.z;
    const float* Bsrc = tmode == 0 ? Phi : Qinit;
    float* dst = tmode == 0 ? dPhiTb : dx;
    int bb = blockIdx.y * 32, jb = blockIdx.x * 32;
    int tx = threadIdx.x, ty = threadIdx.y;
    int t = ty * 16 + tx;
    float acc00 = 0.f, acc01 = 0.f, acc10 = 0.f, acc11 = 0.f;
    for (int k0 = 0; k0 < MDIM; k0 += 32) {
        for (int q = t; q < 1024; q += 256) {
            int kk = q % 32, r = q / 32;
            As[kk][r] = (k0 + kk < MDIM) ? Phix[(bb + r) * MDIM + k0 + kk] : 0.f;
        }
        if (tmode == 0) {
            for (int q = t; q < 1024; q += 256) {
                int kk = q / 32, j = q % 32;
                Bs[kk][j] = (k0 + kk < MDIM && jb + j < NPIX) ? Bsrc[(k0 + kk) * NPIX + jb + j] : 0.f;
            }
        } else {
            for (int q = t; q < 1024; q += 256) {
                int kk = q % 32, j = q / 32;
                Bs[kk][j] = (k0 + kk < MDIM && jb + j < NPIX) ? Bsrc[(jb + j) * MDIM + k0 + kk] : 0.f;
            }
        }
        __syncthreads();
        #pragma unroll
        for (int kk = 0; kk < 32; kk++) {
            float a0 = As[kk][ty*2], a1 = As[kk][ty*2+1];
            float b0 = Bs[kk][tx*2], b1 = Bs[kk][tx*2+1];
            acc00 = fmaf(a0, b0, acc00); acc01 = fmaf(a0, b1, acc01);
            acc10 = fmaf(a1, b0, acc10); acc11 = fmaf(a1, b1, acc11);
        }
        __syncthreads();
    }
    int b0 = bb + ty*2, j0 = jb + tx*2;
    if (j0     < NPIX) dst[(b0  ) * NPIX + j0  ] = acc00;
    if (j0 + 1 < NPIX) dst[(b0  ) * NPIX + j0+1] = acc01;
    if (j0     < NPIX) dst[(b0+1) * NPIX + j0  ] = acc10;
    if (j0 + 1 < NPIX) dst[(b0+1) * NPIX + j0+1] = acc11;
}

// ---------------- conv1 (1 -> 32): z f32 -> x1 bf16 pixel-major ----------------
__global__ __launch_bounds__(128) void k_conv1n(
        const float* __restrict__ z, const float* __restrict__ w1,
        unsigned int* __restrict__ x1out) {
    __shared__ float s_z[SROWS];
    __shared__ float s_w[9 * CC];     // [k][co]
    const int dlt[9] = {-37,-36,-35,-1,0,1,35,36,37};
    int n = blockIdx.x, tid = threadIdx.x;
    for (int i = tid; i < SROWS; i += 128) s_z[i] = 0.f;
    for (int i = tid; i < 9 * CC; i += 128) {
        int o = i / 9, k = i % 9;
        s_w[k * CC + o] = w1[i];
    }
    __syncthreads();
    const float* zb = z + (size_t)n * NPIX;
    for (int p = tid; p < NPIX; p += 128) {
        int y = p / 33, x = p - y * 33;
        s_z[FRONT + (y + 1) * 36 + (x + 1)] = zb[p];
    }
    __syncthreads();
    unsigned int* xo = x1out + (size_t)n * NPIX * 16;
    for (int p = tid; p < NPIX; p += 128) {
        int y = p / 33, x = p - y * 33;
        int pp = FRONT + (y + 1) * 36 + (x + 1);
        float acc[CC];
        #pragma unroll
        for (int co = 0; co < CC; co++) acc[co] = 0.f;
        #pragma unroll
        for (int k = 0; k < 9; k++) {
            float v = s_z[pp + dlt[k]];
            #pragma unroll
            for (int co = 0; co < CC; co++)
                acc[co] = fmaf(v, s_w[k * CC + co], acc[co]);
        }
        unsigned int* row = xo + p * 16;
        #pragma unroll
        for (int j = 0; j < 16; j++) row[j] = bpk(acc[2*j], acc[2*j+1]);
    }
}

// ---------------- tensor conv (32 -> 32) via mma.sync bf16 ----------------
__global__ __launch_bounds__(TC_THREADS) void k_convTC(
        const unsigned int* __restrict__ in, const float* __restrict__ w,
        unsigned int* __restrict__ out, const unsigned int* __restrict__ pre,
        const float* __restrict__ soft, int flags) {
    extern __shared__ char smem[];
    __nv_bfloat16* wt = (__nv_bfloat16*)smem;                 // [32][WT_STRIDE]
    unsigned int* srows = (unsigned int*)(smem + OFF_ROWS);   // SROWS x ROWW u32
    uint32_t rows_addr = smem_to_u32(srows);
    const int dlt[9] = {-37,-36,-35,-1,0,1,35,36,37};
    int tid = threadIdx.x;
    int lane = tid & 31, warp = tid >> 5;
    int n = blockIdx.x;

    // zero input rows
    uint4 z4 = make_uint4(0, 0, 0, 0);
    for (int i = tid; i < SROWS * 5; i += TC_THREADS) ((uint4*)srows)[i] = z4;

    // stage weights transposed: Wt[co][tap*32+ci]
    bool flip = (flags & FLAG_FLIP) != 0;
    for (int idx = tid; idx < CC * CC * 9; idx += TC_THREADS) {
        int kx = idx % 3, ky = (idx / 3) % 3;
        int i = (idx / 9) % CC, o = idx / (9 * CC);
        float v = w[idx];
        int eci, eco, ek;
        if (flip) { eci = o; eco = i; ek = (2 - ky) * 3 + (2 - kx); }
        else      { eci = i; eco = o; ek = ky * 3 + kx; }
        wt[eco * WT_STRIDE + ek * 32 + eci] = __float2bfloat16(v);
    }
    __syncthreads();

    // stage input pixels (fused act / gnorm)
    const uint4* inb = (const uint4*)in + (size_t)n * NPIX * 4;
    bool act_in = (flags & FLAG_ACT_IN) != 0;
    bool gn = (flags & FLAG_GNORM) != 0;
    float thr = 0.f, invthr = 0.f;
    if (gn) { thr = soft[0] * d_gamma; invthr = 1.0f / thr; }
    for (int p = tid; p < NPIX; p += TC_THREADS) {
        int y = p / 33, x = p - y * 33;
        int row = FRONT + (y + 1) * 36 + (x + 1);
        uint4 q0 = inb[p*4+0], q1 = inb[p*4+1], q2 = inb[p*4+2], q3 = inb[p*4+3];
        unsigned int u[16] = {q0.x,q0.y,q0.z,q0.w, q1.x,q1.y,q1.z,q1.w,
                              q2.x,q2.y,q2.z,q2.w, q3.x,q3.y,q3.z,q3.w};
        if (act_in) {
            #pragma unroll
            for (int j = 0; j < 16; j++) {
                float2 f = bupk(u[j]);
                u[j] = bpk(actf(f.x), actf(f.y));
            }
        } else if (gn) {
            float2 f[16];
            float s = 0.f;
            #pragma unroll
            for (int j = 0; j < 16; j++) {
                f[j] = bupk(u[j]);
                s = fmaf(f[j].x, f[j].x, fmaf(f[j].y, f[j].y, s));
            }
            float nrm = sqrtf(s);
            float fac = (nrm > thr) ? (1.0f / fmaxf(nrm, 1e-12f)) : invthr;
            #pragma unroll
            for (int j = 0; j < 16; j++)
                u[j] = bpk(f[j].x * fac, f[j].y * fac);
        }
        uint4* dst = (uint4*)(srows + row * ROWW);
        dst[0] = make_uint4(u[0],u[1],u[2],u[3]);
        dst[1] = make_uint4(u[4],u[5],u[6],u[7]);
        dst[2] = make_uint4(u[8],u[9],u[10],u[11]);
        dst[3] = make_uint4(u[12],u[13],u[14],u[15]);
    }
    __syncthreads();

    unsigned int* outp = out + (size_t)n * NPIX * 16;
    const unsigned int* prep = pre + (size_t)n * NPIX * 16;
    bool actder = (flags & FLAG_ACTDER) != 0;

    for (int tile = warp; tile < NTILES; tile += 8) {
        int p0 = tile * 16;
        int pl = p0 + (lane & 15); if (pl > NPIX - 1) pl = NPIX - 1;
        int y = pl / 33, x = pl - y * 33;
        uint32_t abase = rows_addr
                       + (uint32_t)((FRONT + (y + 1) * 36 + (x + 1)) * 80)
                       + (uint32_t)((lane >> 4) * 16);

        float d[4][4];
        #pragma unroll
        for (int nb = 0; nb < 4; nb++)
            #pragma unroll
            for (int j = 0; j < 4; j++) d[nb][j] = 0.f;

        #pragma unroll
        for (int s = 0; s < KSTEPS; s++) {
            int t = s >> 1, h = s & 1;
            uint32_t aaddr = abase + (uint32_t)(dlt[t] * 80 + h * 32);
            uint32_t a0, a1, a2, a3;
            asm volatile("ldmatrix.sync.aligned.m8n8.x4.shared.b16 {%0,%1,%2,%3}, [%4];"
                         : "=r"(a0), "=r"(a1), "=r"(a2), "=r"(a3) : "r"(aaddr));
            int k0 = s * 16;
            #pragma unroll
            for (int nb = 0; nb < 4; nb++) {
                int row = nb * 8 + (lane >> 2);
                const __nv_bfloat16* wr = wt + row * WT_STRIDE + k0 + (lane & 3) * 2;
                uint32_t b0 = *(const uint32_t*)wr;
                uint32_t b1 = *(const uint32_t*)(wr + 8);
                asm volatile(
                    "mma.sync.aligned.m16n8k16.row.col.f32.bf16.bf16.f32 "
                    "{%0,%1,%2,%3}, {%4,%5,%6,%7}, {%8,%9}, {%0,%1,%2,%3};"
                    : "+f"(d[nb][0]), "+f"(d[nb][1]), "+f"(d[nb][2]), "+f"(d[nb][3])
                    : "r"(a0), "r"(a1), "r"(a2), "r"(a3), "r"(b0), "r"(b1));
            }
        }

        // epilogue: D (16x32 f32) -> pixel-major bf16 u32
        int pA = p0 + (lane >> 2);
        int pB = pA + 8;
        #pragma unroll
        for (int nb = 0; nb < 4; nb++) {
            int ci = nb * 4 + (lane & 3);     // u32 (co-pair) index within pixel
            if (pA < NPIX) {
                float c0 = d[nb][0], c1 = d[nb][1];
                if (actder) {
                    float2 f = bupk(prep[pA * 16 + ci]);
                    c0 *= actdf(f.x); c1 *= actdf(f.y);
                }
                outp[pA * 16 + ci] = bpk(c0, c1);
            }
            if (pB < NPIX) {
                float c2 = d[nb][2], c3 = d[nb][3];
                if (actder) {
                    float2 f = bupk(prep[pB * 16 + ci]);
                    c2 *= actdf(f.x); c3 *= actdf(f.y);
                }
                outp[pB * 16 + ci] = bpk(c2, c3);
            }
        }
    }
}

// ---------------- convT1 (32 -> 1) from bf16 pixel-major, fused update ----------------
__global__ __launch_bounds__(128) void k_convT1n(
        const unsigned int* __restrict__ in, const float* __restrict__ w1,
        const float* __restrict__ z, float* __restrict__ x,
        const float* __restrict__ dotm, float* __restrict__ gphi,
        const float* __restrict__ alphas, const float* __restrict__ betas,
        int phase, int mode, float* __restrict__ out_extra) {
    extern __shared__ char smem[];
    unsigned int* srows = (unsigned int*)smem;     // SROWS * 16 u32
    __shared__ float s_w[CC * 9];                  // flipped [o][k]
    const int dlt[9] = {-37,-36,-35,-1,0,1,35,36,37};
    int n = blockIdx.x, tid = threadIdx.x;

    uint4 z4 = make_uint4(0, 0, 0, 0);
    for (int i = tid; i < SROWS * 4; i += 128) ((uint4*)srows)[i] = z4;
    for (int idx = tid; idx < CC * 9; idx += 128) {
        int o = idx / 9, k = idx % 9;
        int ky = k / 3, kx = k % 3;
        s_w[o * 9 + (2 - ky) * 3 + (2 - kx)] = w1[idx];
    }
    __syncthreads();
    const uint4* inb = (const uint4*)in + (size_t)n * NPIX * 4;
    for (int p = tid; p < NPIX; p += 128) {
        int y = p / 33, xx = p - y * 33;
        int row = FRONT + (y + 1) * 36 + (xx + 1);
        uint4* dst = (uint4*)(srows + row * 16);
        dst[0] = inb[p*4+0]; dst[1] = inb[p*4+1];
        dst[2] = inb[p*4+2]; dst[3] = inb[p*4+3];
    }
    __syncthreads();

    float a = fabsf(alphas[phase]), b = fabsf(betas[phase]);
    float tau = a * b / (a + b);

    for (int p = tid; p < NPIX; p += 128) {
        int y = p / 33, xx = p - y * 33;
        int pp = FRONT + (y + 1) * 36 + (xx + 1);
        float acc = 0.f;
        #pragma unroll
        for (int k = 0; k < 9; k++) {
            const uint4* rp = (const uint4*)(srows + (pp + dlt[k]) * 16);
            uint4 r0 = rp[0], r1 = rp[1], r2 = rp[2], r3 = rp[3];
            unsigned int u[16] = {r0.x,r0.y,r0.z,r0.w, r1.x,r1.y,r1.z,r1.w,
                                  r2.x,r2.y,r2.z,r2.w, r3.x,r3.y,r3.z,r3.w};
            #pragma unroll
            for (int j = 0; j < 16; j++) {
                float2 f = bupk(u[j]);
                acc = fmaf(f.x, s_w[(2*j) * 9 + k], acc);
                acc = fmaf(f.y, s_w[(2*j+1) * 9 + k], acc);
            }
        }
        size_t off = (size_t)n * NPIX + p;
        if (mode == 0) {
            float nx = z[off] - tau * acc;
            x[off] = nx;
            if (out_extra) out_extra[off] = nx;
        } else {
            gphi[off] = dotm[off] + acc;
        }
    }
}

// ---------------- row norms + gamma update ----------------
__global__ void k_rownorm(const float* __restrict__ gphi) {
    __shared__ float red[256];
    int bidx = blockIdx.x;
    float s = 0.f;
    for (int j = threadIdx.x; j < NPIX; j += 256) {
        float v = gphi[(size_t)bidx * NPIX + j];
        s = fmaf(v, v, s);
    }
    red[threadIdx.x] = s;
    __syncthreads();
    for (int off = 128; off > 0; off >>= 1) {
        if (threadIdx.x < off) red[threadIdx.x] += red[threadIdx.x + off];
        __syncthreads();
    }
    if (threadIdx.x == 0) d_ngrad[bidx] = sqrtf(red[0]);
}

__global__ void k_gamma(const float* __restrict__ soft_thr) {
    __shared__ float red[256];
    red[threadIdx.x] = d_ngrad[threadIdx.x];
    __syncthreads();
    for (int off = 128; off > 0; off >>= 1) {
        if (threadIdx.x < off) red[threadIdx.x] += red[threadIdx.x + off];
        __syncthreads();
    }
    if (threadIdx.x == 0) {
        float mean = red[0] / (float)BB;
        float g = d_gamma;
        if (mean < 15000.0f * g * soft_thr[0]) g *= 0.9f;
        d_gamma = g;
    }
}

// ---------------- host orchestration ----------------
static void grad_r_chain(const float* src, const float* c1, const float* c2,
                         const float* c3, const float* c4, const float* soft,
                         unsigned int* px1, unsigned int* px2, unsigned int* px3,
                         unsigned int* pg, unsigned int* pbA,
                         const float* pz, float* px, const float* pdotm, float* pgphi,
                         const float* alphas, const float* betas,
                         int phase, int mode, float* out_extra) {
    k_conv1n<<<BB, 128>>>(src, c1, px1);
    k_convTC<<<BB, TC_THREADS, SMEM_TC>>>(px1, c2, px2, px1, soft, FLAG_ACT_IN);
    k_convTC<<<BB, TC_THREADS, SMEM_TC>>>(px2, c3, px3, px1, soft, FLAG_ACT_IN);
    k_convTC<<<BB, TC_THREADS, SMEM_TC>>>(px3, c4, pg,  px1, soft, FLAG_ACT_IN);
    k_convTC<<<BB, TC_THREADS, SMEM_TC>>>(pg,  c4, pbA, px3, soft, FLAG_FLIP | FLAG_ACTDER | FLAG_GNORM);
    k_convTC<<<BB, TC_THREADS, SMEM_TC>>>(pbA, c3, pg,  px2, soft, FLAG_FLIP | FLAG_ACTDER);
    k_convTC<<<BB, TC_THREADS, SMEM_TC>>>(pg,  c2, pbA, px1, soft, FLAG_FLIP | FLAG_ACTDER);
    k_convT1n<<<BB, 128, SMEM_T1N>>>(pbA, c1, pz, px, pdotm, pgphi,
                                     alphas, betas, phase, mode, out_extra);
}

extern "C" void kernel_launch(void* const* d_in, const int* in_sizes, int n_in,
                              void* d_out, int out_size) {
    (void)in_sizes; (void)n_in; (void)out_size;
    const float* Phix   = (const float*)d_in[0];
    const float* Phi    = (const float*)d_in[1];
    const float* Qinit  = (const float*)d_in[2];
    const float* soft   = (const float*)d_in[3];
    const float* alphas = (const float*)d_in[4];
    const float* betas  = (const float*)d_in[5];
    const float* c1     = (const float*)d_in[6];
    const float* c2     = (const float*)d_in[7];
    const float* c3     = (const float*)d_in[8];
    const float* c4     = (const float*)d_in[9];
    float* out = (float*)d_out;

    cudaFuncSetAttribute(k_convTC,  cudaFuncAttributeMaxDynamicSharedMemorySize, SMEM_TC);
    cudaFuncSetAttribute(k_convT1n, cudaFuncAttributeMaxDynamicSharedMemorySize, SMEM_T1N);

    float *px, *pz, *pgphi, *pdotm, *pPhiTb;
    unsigned int *px1, *px2, *px3, *pg, *pbA;
    cudaGetSymbolAddress((void**)&px,     d_x);
    cudaGetSymbolAddress((void**)&pz,     d_z);
    cudaGetSymbolAddress((void**)&pgphi,  d_gphi);
    cudaGetSymbolAddress((void**)&pdotm,  d_dotm);
    cudaGetSymbolAddress((void**)&px1,    d_x1);
    cudaGetSymbolAddress((void**)&px2,    d_x2);
    cudaGetSymbolAddress((void**)&px3,    d_x3);
    cudaGetSymbolAddress((void**)&pg,     d_g);
    cudaGetSymbolAddress((void**)&pbA,    d_bA);
    cudaGetSymbolAddress((void**)&pPhiTb, d_PhiTb);

    dim3 tb16(16, 16);
    k_phitphi64<<<dim3(18, 18), tb16>>>(Phi);                       // + gamma init
    k_setupF<<<dim3(35, 8, 2), tb16>>>(Phix, Phi, Qinit, pPhiTb, px);

    for (int p = 0; p < 3; p++) {
        if (p == 0)
            k_gemmP<<<dim3(18, 4), tb16>>>(px, pz, alphas, p, 0);
        else
            k_zstep<<<BB, 256>>>(px, pz, alphas, p);
        grad_r_chain(pz, c1, c2, c3, c4, soft, px1, px2, px3, pg, pbA,
                     pz, px, pdotm, pgphi, alphas, betas, p, 0,
                     (p == 2) ? out : nullptr);
        if (p < 2) {
            k_gemmP<<<dim3(18, 4), tb16>>>(px, pdotm, alphas, p, 1);
            grad_r_chain(px, c1, c2, c3, c4, soft, px1, px2, px3, pg, pbA,
                         pz, px, pdotm, pgphi, alphas, betas, p, 1, nullptr);
            k_rownorm<<<BB, 256>>>(pgphi);
            k_gamma<<<1, 256>>>(soft);
        }
    }
}

// round 11
// speedup vs baseline: 3.0601x; 1.2640x over previous
#include <cuda_runtime.h>
#include <cuda_bf16.h>
#include <math.h>
#include <cstdint>

#define BB   256
#define NPIX 1089
#define MDIM 272
#define CC   32

#define FLAG_ACT_IN 1
#define FLAG_FLIP   2
#define FLAG_ACTDER 4
#define FLAG_GNORM  8

// tensor-conv geometry
#define TC_THREADS 256
#define T1_THREADS 256
#define FRONT   40            /* zero rows before padded-pixel 0 */
#define SROWS   1360
#define ROWW    20            /* u32 per smem row (80B stride, conflict-free ldmatrix) */
#define NTILES  69            /* ceil(1089/16) pixel tiles */
#define KSTEPS  18            /* 9 taps * 32 ci / 16 */
#define WT_STRIDE 290         /* bf16 per Wt row (32 co rows) */

#define OFF_ROWS (CC * WT_STRIDE * 2)            /* 18560 */
#define SMEM_TC  (OFF_ROWS + SROWS * ROWW * 4)   /* 127360 */
#define SMEM_T1N (SROWS * 64)                    /* 87040 */

// ---------------- device state (static, no allocation) ----------------
__device__ float d_P[NPIX*NPIX];
__device__ float d_PhiTb[BB*NPIX];
__device__ float d_x[BB*NPIX];
__device__ float d_z[BB*NPIX];
__device__ float d_gphi[BB*NPIX];
__device__ float d_dotm[BB*NPIX];
// pixel-major bf16 tensors: [image][pixel][32ch] as 16 u32 per pixel
__device__ unsigned int d_x1[BB*NPIX*16];
__device__ unsigned int d_x2[BB*NPIX*16];
__device__ unsigned int d_x3[BB*NPIX*16];
__device__ unsigned int d_g [BB*NPIX*16];
__device__ unsigned int d_bA[BB*NPIX*16];
__device__ float d_ngrad[BB];
__device__ float d_gamma;

__device__ __forceinline__ uint32_t smem_to_u32(const void* p) {
    uint32_t a;
    asm("{ .reg .u64 t; cvta.to.shared.u64 t, %1; cvt.u32.u64 %0, t; }" : "=r"(a) : "l"(p));
    return a;
}

// ---------------- bf16 pack/unpack ----------------
__device__ __forceinline__ float2 bupk(unsigned int u) {
    __nv_bfloat162 t = *reinterpret_cast<__nv_bfloat162*>(&u);
    return __bfloat1622float2(t);
}
__device__ __forceinline__ unsigned int bpk(float a, float b) {
    __nv_bfloat162 t = __floats2bfloat162_rn(a, b);
    return *reinterpret_cast<unsigned int*>(&t);
}

// ---------------- activation (eq. 33), DELTA = 0.01 ----------------
__device__ __forceinline__ float actf(float v) {
    if (fabsf(v) > 0.01f) return fmaxf(v, 0.0f);
    return fmaf(v*v, 25.0f, fmaf(v, 0.5f, 0.0025f));
}
__device__ __forceinline__ float actdf(float v) {
    if (fabsf(v) > 0.01f) return v > 0.0f ? 1.0f : 0.0f;
    return fmaf(v, 50.0f, 0.5f);
}

// ---------------- GEMM: P = Phi^T Phi ----------------
__global__ void k_phitphi64(const float* __restrict__ Phi) {
    if (blockIdx.x == 0 && blockIdx.y == 0 && threadIdx.x == 0 && threadIdx.y == 0)
        d_gamma = 1.0f;
    __shared__ float As[16][68];
    __shared__ float Bs[16][68];
    int ib = blockIdx.y * 64, jb = blockIdx.x * 64;
    int tx = threadIdx.x, ty = threadIdx.y;
    int t = ty * 16 + tx;
    float acc[4][4];
    #pragma unroll
    for (int r = 0; r < 4; r++)
        #pragma unroll
        for (int c = 0; c < 4; c++) acc[r][c] = 0.f;
    for (int k0 = 0; k0 < MDIM; k0 += 16) {
        #pragma unroll
        for (int q = t; q < 1024; q += 256) {
            int kk = q / 64, r = q % 64;
            As[kk][r] = (ib + r < NPIX) ? Phi[(k0 + kk) * NPIX + ib + r] : 0.f;
            Bs[kk][r] = (jb + r < NPIX) ? Phi[(k0 + kk) * NPIX + jb + r] : 0.f;
        }
        __syncthreads();
        #pragma unroll
        for (int kk = 0; kk < 16; kk++) {
            float4 a4 = *(const float4*)&As[kk][ty * 4];
            float4 b4 = *(const float4*)&Bs[kk][tx * 4];
            float ar[4] = {a4.x, a4.y, a4.z, a4.w};
            float br[4] = {b4.x, b4.y, b4.z, b4.w};
            #pragma unroll
            for (int r = 0; r < 4; r++)
                #pragma unroll
                for (int c = 0; c < 4; c++)
                    acc[r][c] = fmaf(ar[r], br[c], acc[r][c]);
        }
        __syncthreads();
    }
    #pragma unroll
    for (int r = 0; r < 4; r++) {
        int i = ib + ty * 4 + r;
        if (i >= NPIX) continue;
        #pragma unroll
        for (int c = 0; c < 4; c++) {
            int j = jb + tx * 4 + c;
            if (j < NPIX) d_P[i * NPIX + j] = acc[r][c];
        }
    }
}

// ---------------- phase GEMM ----------------
__global__ void k_gemmP(const float* __restrict__ src, float* __restrict__ dst,
                        const float* __restrict__ alphas, int phase, int mode) {
    __shared__ float As[16][68];
    __shared__ float Bs[16][68];
    int bb = blockIdx.y * 64, jb = blockIdx.x * 64;
    int tx = threadIdx.x, ty = threadIdx.y;
    int t = ty * 16 + tx;
    float acc[4][4];
    #pragma unroll
    for (int r = 0; r < 4; r++)
        #pragma unroll
        for (int c = 0; c < 4; c++) acc[r][c] = 0.f;
    for (int k0 = 0; k0 < NPIX; k0 += 16) {
        #pragma unroll
        for (int q = t; q < 1024; q += 256) {
            int r = q / 16, kk = q % 16;
            As[kk][r] = (k0 + kk < NPIX) ? src[(bb + r) * NPIX + k0 + kk] : 0.f;
        }
        #pragma unroll
        for (int q = t; q < 1024; q += 256) {
            int kk = q / 64, c = q % 64;
            Bs[kk][c] = (k0 + kk < NPIX && jb + c < NPIX) ? d_P[(k0 + kk) * NPIX + jb + c] : 0.f;
        }
        __syncthreads();
        #pragma unroll
        for (int kk = 0; kk < 16; kk++) {
            float4 a4 = *(const float4*)&As[kk][ty * 4];
            float4 b4 = *(const float4*)&Bs[kk][tx * 4];
            float ar[4] = {a4.x, a4.y, a4.z, a4.w};
            float br[4] = {b4.x, b4.y, b4.z, b4.w};
            #pragma unroll
            for (int r = 0; r < 4; r++)
                #pragma unroll
                for (int c = 0; c < 4; c++)
                    acc[r][c] = fmaf(ar[r], br[c], acc[r][c]);
        }
        __syncthreads();
    }
    float alpha = fabsf(alphas[phase]);
    #pragma unroll
    for (int r = 0; r < 4; r++) {
        int b = bb + ty * 4 + r;
        #pragma unroll
        for (int c = 0; c < 4; c++) {
            int j = jb + tx * 4 + c;
            if (j < NPIX) {
                float dot = acc[r][c];
                float ptb = d_PhiTb[b * NPIX + j];
                if (mode == 0)
                    dst[b * NPIX + j] = src[b * NPIX + j] + alpha * (ptb - dot);
                else
                    dst[b * NPIX + j] = dot - ptb;
            }
        }
    }
}

__global__ void k_zstep(const float* __restrict__ x, float* __restrict__ z,
                        const float* __restrict__ alphas, int phase) {
    float alpha = fabsf(alphas[phase]);
    size_t base = (size_t)blockIdx.x * NPIX;
    for (int j = threadIdx.x; j < NPIX; j += blockDim.x)
        z[base + j] = x[base + j] - alpha * d_dotm[base + j];
}

__global__ void k_setupF(const float* __restrict__ Phix, const float* __restrict__ Phi,
                         const float* __restrict__ Qinit,
                         float* __restrict__ dPhiTb, float* __restrict__ dx) {
    __shared__ float As[32][33];
    __shared__ float Bs[32][33];
    int tmode = blockIdx.z;
    const float* Bsrc = tmode == 0 ? Phi : Qinit;
    float* dst = tmode == 0 ? dPhiTb : dx;
    int bb = blockIdx.y * 32, jb = blockIdx.x * 32;
    int tx = threadIdx.x, ty = threadIdx.y;
    int t = ty * 16 + tx;
    float acc00 = 0.f, acc01 = 0.f, acc10 = 0.f, acc11 = 0.f;
    for (int k0 = 0; k0 < MDIM; k0 += 32) {
        for (int q = t; q < 1024; q += 256) {
            int kk = q % 32, r = q / 32;
            As[kk][r] = (k0 + kk < MDIM) ? Phix[(bb + r) * MDIM + k0 + kk] : 0.f;
        }
        if (tmode == 0) {
            for (int q = t; q < 1024; q += 256) {
                int kk = q / 32, j = q % 32;
                Bs[kk][j] = (k0 + kk < MDIM && jb + j < NPIX) ? Bsrc[(k0 + kk) * NPIX + jb + j] : 0.f;
            }
        } else {
            for (int q = t; q < 1024; q += 256) {
                int kk = q % 32, j = q / 32;
                Bs[kk][j] = (k0 + kk < MDIM && jb + j < NPIX) ? Bsrc[(jb + j) * MDIM + k0 + kk] : 0.f;
            }
        }
        __syncthreads();
        #pragma unroll
        for (int kk = 0; kk < 32; kk++) {
            float a0 = As[kk][ty*2], a1 = As[kk][ty*2+1];
            float b0 = Bs[kk][tx*2], b1 = Bs[kk][tx*2+1];
            acc00 = fmaf(a0, b0, acc00); acc01 = fmaf(a0, b1, acc01);
            acc10 = fmaf(a1, b0, acc10); acc11 = fmaf(a1, b1, acc11);
        }
        __syncthreads();
    }
    int b0 = bb + ty*2, j0 = jb + tx*2;
    if (j0     < NPIX) dst[(b0  ) * NPIX + j0  ] = acc00;
    if (j0 + 1 < NPIX) dst[(b0  ) * NPIX + j0+1] = acc01;
    if (j0     < NPIX) dst[(b0+1) * NPIX + j0  ] = acc10;
    if (j0 + 1 < NPIX) dst[(b0+1) * NPIX + j0+1] = acc11;
}

// ---------------- conv1 (1 -> 32): z f32 -> x1 bf16 pixel-major ----------------
// 8-channel chunks keep register count low.
__global__ __launch_bounds__(256) void k_conv1n(
        const float* __restrict__ z, const float* __restrict__ w1,
        unsigned int* __restrict__ x1out) {
    __shared__ float s_z[SROWS];
    __shared__ float s_w[9 * CC];     // [k][co]
    const int dlt[9] = {-37,-36,-35,-1,0,1,35,36,37};
    int n = blockIdx.x, tid = threadIdx.x;
    for (int i = tid; i < SROWS; i += 256) s_z[i] = 0.f;
    for (int i = tid; i < 9 * CC; i += 256) {
        int o = i / 9, k = i % 9;
        s_w[k * CC + o] = w1[i];
    }
    __syncthreads();
    const float* zb = z + (size_t)n * NPIX;
    for (int p = tid; p < NPIX; p += 256) {
        int y = p / 33, x = p - y * 33;
        s_z[FRONT + (y + 1) * 36 + (x + 1)] = zb[p];
    }
    __syncthreads();
    unsigned int* xo = x1out + (size_t)n * NPIX * 16;
    for (int p = tid; p < NPIX; p += 256) {
        int y = p / 33, x = p - y * 33;
        int pp = FRONT + (y + 1) * 36 + (x + 1);
        float zv[9];
        #pragma unroll
        for (int k = 0; k < 9; k++) zv[k] = s_z[pp + dlt[k]];
        unsigned int* row = xo + p * 16;
        #pragma unroll
        for (int ch = 0; ch < 4; ch++) {           // 8 channels per chunk
            float acc[8];
            #pragma unroll
            for (int j = 0; j < 8; j++) acc[j] = 0.f;
            #pragma unroll
            for (int k = 0; k < 9; k++) {
                float4 w0 = *(const float4*)(s_w + k * CC + ch * 8);
                float4 w1v = *(const float4*)(s_w + k * CC + ch * 8 + 4);
                acc[0] = fmaf(zv[k], w0.x, acc[0]);
                acc[1] = fmaf(zv[k], w0.y, acc[1]);
                acc[2] = fmaf(zv[k], w0.z, acc[2]);
                acc[3] = fmaf(zv[k], w0.w, acc[3]);
                acc[4] = fmaf(zv[k], w1v.x, acc[4]);
                acc[5] = fmaf(zv[k], w1v.y, acc[5]);
                acc[6] = fmaf(zv[k], w1v.z, acc[6]);
                acc[7] = fmaf(zv[k], w1v.w, acc[7]);
            }
            uint4 o4 = make_uint4(bpk(acc[0], acc[1]), bpk(acc[2], acc[3]),
                                  bpk(acc[4], acc[5]), bpk(acc[6], acc[7]));
            *(uint4*)(row + ch * 4) = o4;
        }
    }
}

// ---------------- tensor conv (32 -> 32) via mma.sync bf16, B in registers ---------
__global__ __launch_bounds__(TC_THREADS) void k_convTC(
        const unsigned int* __restrict__ in, const float* __restrict__ w,
        unsigned int* __restrict__ out, const unsigned int* __restrict__ pre,
        const float* __restrict__ soft, int flags) {
    extern __shared__ char smem[];
    __nv_bfloat16* wt = (__nv_bfloat16*)smem;                 // [32][WT_STRIDE]
    unsigned int* srows = (unsigned int*)(smem + OFF_ROWS);   // SROWS x ROWW u32
    uint32_t rows_addr = smem_to_u32(srows);
    const int dlt[9] = {-37,-36,-35,-1,0,1,35,36,37};
    int tid = threadIdx.x;
    int lane = tid & 31, warp = tid >> 5;
    int n = blockIdx.x;

    // zero input rows
    uint4 z4 = make_uint4(0, 0, 0, 0);
    for (int i = tid; i < SROWS * 5; i += TC_THREADS) ((uint4*)srows)[i] = z4;

    // stage weights transposed: Wt[co][tap*32+ci]
    bool flip = (flags & FLAG_FLIP) != 0;
    for (int idx = tid; idx < CC * CC * 9; idx += TC_THREADS) {
        int kx = idx % 3, ky = (idx / 3) % 3;
        int i = (idx / 9) % CC, o = idx / (9 * CC);
        float v = w[idx];
        int eci, eco, ek;
        if (flip) { eci = o; eco = i; ek = (2 - ky) * 3 + (2 - kx); }
        else      { eci = i; eco = o; ek = ky * 3 + kx; }
        wt[eco * WT_STRIDE + ek * 32 + eci] = __float2bfloat16(v);
    }
    __syncthreads();

    // stage input pixels (fused act / gnorm)
    const uint4* inb = (const uint4*)in + (size_t)n * NPIX * 4;
    bool act_in = (flags & FLAG_ACT_IN) != 0;
    bool gn = (flags & FLAG_GNORM) != 0;
    float thr = 0.f, invthr = 0.f;
    if (gn) { thr = soft[0] * d_gamma; invthr = 1.0f / thr; }
    for (int p = tid; p < NPIX; p += TC_THREADS) {
        int y = p / 33, x = p - y * 33;
        int row = FRONT + (y + 1) * 36 + (x + 1);
        uint4 q0 = inb[p*4+0], q1 = inb[p*4+1], q2 = inb[p*4+2], q3 = inb[p*4+3];
        unsigned int u[16] = {q0.x,q0.y,q0.z,q0.w, q1.x,q1.y,q1.z,q1.w,
                              q2.x,q2.y,q2.z,q2.w, q3.x,q3.y,q3.z,q3.w};
        if (act_in) {
            #pragma unroll
            for (int j = 0; j < 16; j++) {
                float2 f = bupk(u[j]);
                u[j] = bpk(actf(f.x), actf(f.y));
            }
        } else if (gn) {
            float2 f[16];
            float s = 0.f;
            #pragma unroll
            for (int j = 0; j < 16; j++) {
                f[j] = bupk(u[j]);
                s = fmaf(f[j].x, f[j].x, fmaf(f[j].y, f[j].y, s));
            }
            float nrm = sqrtf(s);
            float fac = (nrm > thr) ? (1.0f / fmaxf(nrm, 1e-12f)) : invthr;
            #pragma unroll
            for (int j = 0; j < 16; j++)
                u[j] = bpk(f[j].x * fac, f[j].y * fac);
        }
        uint4* dst = (uint4*)(srows + row * ROWW);
        dst[0] = make_uint4(u[0],u[1],u[2],u[3]);
        dst[1] = make_uint4(u[4],u[5],u[6],u[7]);
        dst[2] = make_uint4(u[8],u[9],u[10],u[11]);
        dst[3] = make_uint4(u[12],u[13],u[14],u[15]);
    }
    __syncthreads();

    // preload ALL B fragments into registers (tile-invariant)
    uint32_t breg[KSTEPS][4][2];
    {
        int brow = lane >> 2, bcol = (lane & 3) * 2;
        #pragma unroll
        for (int s = 0; s < KSTEPS; s++) {
            #pragma unroll
            for (int nb = 0; nb < 4; nb++) {
                const __nv_bfloat16* wr = wt + (nb * 8 + brow) * WT_STRIDE + s * 16 + bcol;
                breg[s][nb][0] = *(const uint32_t*)wr;
                breg[s][nb][1] = *(const uint32_t*)(wr + 8);
            }
        }
    }

    unsigned int* outp = out + (size_t)n * NPIX * 16;
    const unsigned int* prep = pre + (size_t)n * NPIX * 16;
    bool actder = (flags & FLAG_ACTDER) != 0;

    for (int tile = warp; tile < NTILES; tile += 8) {
        int p0 = tile * 16;
        int pl = p0 + (lane & 15); if (pl > NPIX - 1) pl = NPIX - 1;
        int y = pl / 33, x = pl - y * 33;
        uint32_t abase = rows_addr
                       + (uint32_t)((FRONT + (y + 1) * 36 + (x + 1)) * 80)
                       + (uint32_t)((lane >> 4) * 16);

        float d[4][4];
        #pragma unroll
        for (int nb = 0; nb < 4; nb++)
            #pragma unroll
            for (int j = 0; j < 4; j++) d[nb][j] = 0.f;

        #pragma unroll
        for (int s = 0; s < KSTEPS; s++) {
            int t = s >> 1, h = s & 1;
            uint32_t aaddr = abase + (uint32_t)(dlt[t] * 80 + h * 32);
            uint32_t a0, a1, a2, a3;
            asm volatile("ldmatrix.sync.aligned.m8n8.x4.shared.b16 {%0,%1,%2,%3}, [%4];"
                         : "=r"(a0), "=r"(a1), "=r"(a2), "=r"(a3) : "r"(aaddr));
            #pragma unroll
            for (int nb = 0; nb < 4; nb++) {
                asm volatile(
                    "mma.sync.aligned.m16n8k16.row.col.f32.bf16.bf16.f32 "
                    "{%0,%1,%2,%3}, {%4,%5,%6,%7}, {%8,%9}, {%0,%1,%2,%3};"
                    : "+f"(d[nb][0]), "+f"(d[nb][1]), "+f"(d[nb][2]), "+f"(d[nb][3])
                    : "r"(a0), "r"(a1), "r"(a2), "r"(a3),
                      "r"(breg[s][nb][0]), "r"(breg[s][nb][1]));
            }
        }

        // epilogue: D (16x32 f32) -> pixel-major bf16 u32
        int pA = p0 + (lane >> 2);
        int pB = pA + 8;
        #pragma unroll
        for (int nb = 0; nb < 4; nb++) {
            int ci = nb * 4 + (lane & 3);     // u32 (co-pair) index within pixel
            if (pA < NPIX) {
                float c0 = d[nb][0], c1 = d[nb][1];
                if (actder) {
                    float2 f = bupk(prep[pA * 16 + ci]);
                    c0 *= actdf(f.x); c1 *= actdf(f.y);
                }
                outp[pA * 16 + ci] = bpk(c0, c1);
            }
            if (pB < NPIX) {
                float c2 = d[nb][2], c3 = d[nb][3];
                if (actder) {
                    float2 f = bupk(prep[pB * 16 + ci]);
                    c2 *= actdf(f.x); c3 *= actdf(f.y);
                }
                outp[pB * 16 + ci] = bpk(c2, c3);
            }
        }
    }
}

// ---------------- convT1 (32 -> 1) from bf16 pixel-major, fused update ----------------
__global__ __launch_bounds__(T1_THREADS) void k_convT1n(
        const unsigned int* __restrict__ in, const float* __restrict__ w1,
        const float* __restrict__ z, float* __restrict__ x,
        const float* __restrict__ dotm, float* __restrict__ gphi,
        const float* __restrict__ alphas, const float* __restrict__ betas,
        int phase, int mode, float* __restrict__ out_extra) {
    extern __shared__ char smem[];
    unsigned int* srows = (unsigned int*)smem;     // SROWS * 16 u32
    __shared__ float s_w[CC * 9];                  // flipped [o][k]
    const int dlt[9] = {-37,-36,-35,-1,0,1,35,36,37};
    int n = blockIdx.x, tid = threadIdx.x;

    uint4 z4 = make_uint4(0, 0, 0, 0);
    for (int i = tid; i < SROWS * 4; i += T1_THREADS) ((uint4*)srows)[i] = z4;
    for (int idx = tid; idx < CC * 9; idx += T1_THREADS) {
        int o = idx / 9, k = idx % 9;
        int ky = k / 3, kx = k % 3;
        s_w[o * 9 + (2 - ky) * 3 + (2 - kx)] = w1[idx];
    }
    __syncthreads();
    const uint4* inb = (const uint4*)in + (size_t)n * NPIX * 4;
    for (int p = tid; p < NPIX; p += T1_THREADS) {
        int y = p / 33, xx = p - y * 33;
        int row = FRONT + (y + 1) * 36 + (xx + 1);
        uint4* dst = (uint4*)(srows + row * 16);
        dst[0] = inb[p*4+0]; dst[1] = inb[p*4+1];
        dst[2] = inb[p*4+2]; dst[3] = inb[p*4+3];
    }
    __syncthreads();

    float a = fabsf(alphas[phase]), b = fabsf(betas[phase]);
    float tau = a * b / (a + b);

    for (int p = tid; p < NPIX; p += T1_THREADS) {
        int y = p / 33, xx = p - y * 33;
        int pp = FRONT + (y + 1) * 36 + (xx + 1);
        float acc = 0.f;
        #pragma unroll
        for (int k = 0; k < 9; k++) {
            const uint4* rp = (const uint4*)(srows + (pp + dlt[k]) * 16);
            uint4 r0 = rp[0], r1 = rp[1], r2 = rp[2], r3 = rp[3];
            unsigned int u[16] = {r0.x,r0.y,r0.z,r0.w, r1.x,r1.y,r1.z,r1.w,
                                  r2.x,r2.y,r2.z,r2.w, r3.x,r3.y,r3.z,r3.w};
            #pragma unroll
            for (int j = 0; j < 16; j++) {
                float2 f = bupk(u[j]);
                acc = fmaf(f.x, s_w[(2*j) * 9 + k], acc);
                acc = fmaf(f.y, s_w[(2*j+1) * 9 + k], acc);
            }
        }
        size_t off = (size_t)n * NPIX + p;
        if (mode == 0) {
            float nx = z[off] - tau * acc;
            x[off] = nx;
            if (out_extra) out_extra[off] = nx;
        } else {
            gphi[off] = dotm[off] + acc;
        }
    }
}

// ---------------- row norms + gamma update ----------------
__global__ void k_rownorm(const float* __restrict__ gphi) {
    __shared__ float red[256];
    int bidx = blockIdx.x;
    float s = 0.f;
    for (int j = threadIdx.x; j < NPIX; j += 256) {
        float v = gphi[(size_t)bidx * NPIX + j];
        s = fmaf(v, v, s);
    }
    red[threadIdx.x] = s;
    __syncthreads();
    for (int off = 128; off > 0; off >>= 1) {
        if (threadIdx.x < off) red[threadIdx.x] += red[threadIdx.x + off];
        __syncthreads();
    }
    if (threadIdx.x == 0) d_ngrad[bidx] = sqrtf(red[0]);
}

__global__ void k_gamma(const float* __restrict__ soft_thr) {
    __shared__ float red[256];
    red[threadIdx.x] = d_ngrad[threadIdx.x];
    __syncthreads();
    for (int off = 128; off > 0; off >>= 1) {
        if (threadIdx.x < off) red[threadIdx.x] += red[threadIdx.x + off];
        __syncthreads();
    }
    if (threadIdx.x == 0) {
        float mean = red[0] / (float)BB;
        float g = d_gamma;
        if (mean < 15000.0f * g * soft_thr[0]) g *= 0.9f;
        d_gamma = g;
    }
}

// ---------------- host orchestration ----------------
static void grad_r_chain(const float* src, const float* c1, const float* c2,
                         const float* c3, const float* c4, const float* soft,
                         unsigned int* px1, unsigned int* px2, unsigned int* px3,
                         unsigned int* pg, unsigned int* pbA,
                         const float* pz, float* px, const float* pdotm, float* pgphi,
                         const float* alphas, const float* betas,
                         int phase, int mode, float* out_extra) {
    k_conv1n<<<BB, 256>>>(src, c1, px1);
    k_convTC<<<BB, TC_THREADS, SMEM_TC>>>(px1, c2, px2, px1, soft, FLAG_ACT_IN);
    k_convTC<<<BB, TC_THREADS, SMEM_TC>>>(px2, c3, px3, px1, soft, FLAG_ACT_IN);
    k_convTC<<<BB, TC_THREADS, SMEM_TC>>>(px3, c4, pg,  px1, soft, FLAG_ACT_IN);
    k_convTC<<<BB, TC_THREADS, SMEM_TC>>>(pg,  c4, pbA, px3, soft, FLAG_FLIP | FLAG_ACTDER | FLAG_GNORM);
    k_convTC<<<BB, TC_THREADS, SMEM_TC>>>(pbA, c3, pg,  px2, soft, FLAG_FLIP | FLAG_ACTDER);
    k_convTC<<<BB, TC_THREADS, SMEM_TC>>>(pg,  c2, pbA, px1, soft, FLAG_FLIP | FLAG_ACTDER);
    k_convT1n<<<BB, T1_THREADS, SMEM_T1N>>>(pbA, c1, pz, px, pdotm, pgphi,
                                            alphas, betas, phase, mode, out_extra);
}

extern "C" void kernel_launch(void* const* d_in, const int* in_sizes, int n_in,
                              void* d_out, int out_size) {
    (void)in_sizes; (void)n_in; (void)out_size;
    const float* Phix   = (const float*)d_in[0];
    const float* Phi    = (const float*)d_in[1];
    const float* Qinit  = (const float*)d_in[2];
    const float* soft   = (const float*)d_in[3];
    const float* alphas = (const float*)d_in[4];
    const float* betas  = (const float*)d_in[5];
    const float* c1     = (const float*)d_in[6];
    const float* c2     = (const float*)d_in[7];
    const float* c3     = (const float*)d_in[8];
    const float* c4     = (const float*)d_in[9];
    float* out = (float*)d_out;

    cudaFuncSetAttribute(k_convTC,  cudaFuncAttributeMaxDynamicSharedMemorySize, SMEM_TC);
    cudaFuncSetAttribute(k_convT1n, cudaFuncAttributeMaxDynamicSharedMemorySize, SMEM_T1N);

    float *px, *pz, *pgphi, *pdotm, *pPhiTb;
    unsigned int *px1, *px2, *px3, *pg, *pbA;
    cudaGetSymbolAddress((void**)&px,     d_x);
    cudaGetSymbolAddress((void**)&pz,     d_z);
    cudaGetSymbolAddress((void**)&pgphi,  d_gphi);
    cudaGetSymbolAddress((void**)&pdotm,  d_dotm);
    cudaGetSymbolAddress((void**)&px1,    d_x1);
    cudaGetSymbolAddress((void**)&px2,    d_x2);
    cudaGetSymbolAddress((void**)&px3,    d_x3);
    cudaGetSymbolAddress((void**)&pg,     d_g);
    cudaGetSymbolAddress((void**)&pbA,    d_bA);
    cudaGetSymbolAddress((void**)&pPhiTb, d_PhiTb);

    dim3 tb16(16, 16);
    k_phitphi64<<<dim3(18, 18), tb16>>>(Phi);                       // + gamma init
    k_setupF<<<dim3(35, 8, 2), tb16>>>(Phix, Phi, Qinit, pPhiTb, px);

    for (int p = 0; p < 3; p++) {
        if (p == 0)
            k_gemmP<<<dim3(18, 4), tb16>>>(px, pz, alphas, p, 0);
        else
            k_zstep<<<BB, 256>>>(px, pz, alphas, p);
        grad_r_chain(pz, c1, c2, c3, c4, soft, px1, px2, px3, pg, pbA,
                     pz, px, pdotm, pgphi, alphas, betas, p, 0,
                     (p == 2) ? out : nullptr);
        if (p < 2) {
            k_gemmP<<<dim3(18, 4), tb16>>>(px, pdotm, alphas, p, 1);
            grad_r_chain(px, c1, c2, c3, c4, soft, px1, px2, px3, pg, pbA,
                         pz, px, pdotm, pgphi, alphas, betas, p, 1, nullptr);
            k_rownorm<<<BB, 256>>>(pgphi);
            k_gamma<<<1, 256>>>(soft);
        }
    }
}

// round 12
// speedup vs baseline: 3.3884x; 1.1073x over previous
#include <cuda_runtime.h>
#include <cuda_bf16.h>
#include <math.h>
#include <cstdint>

#define BB   256
#define NPIX 1089
#define MDIM 272
#define CC   32

#define FLAG_ACT_IN 1
#define FLAG_FLIP   2
#define FLAG_ACTDER 4
#define FLAG_GNORM  8
#define FLAG_CONV1  16

// tensor-conv geometry
#define TC_THREADS 256
#define T1_THREADS 256
#define FRONT   40            /* zero rows before padded-pixel 0 */
#define SROWS   1360
#define ROWW    20            /* u32 per smem row (80B stride, conflict-free ldmatrix) */
#define NTILES  69            /* ceil(1089/16) pixel tiles */
#define KSTEPS  18            /* 9 taps * 32 ci / 16 */
#define WT_STRIDE 290         /* bf16 per Wt row (32 co rows) */

#define OFF_ROWS (CC * WT_STRIDE * 2)            /* 18560 */
#define SMEM_TC  (OFF_ROWS + SROWS * ROWW * 4)   /* 127360 */
#define OFF_SZ   SMEM_TC
#define OFF_SW1  (OFF_SZ + SROWS * 4)            /* 132800 */
#define SMEM_TC2 (OFF_SW1 + 9 * CC * 4)          /* 133952 */
#define SMEM_T1N (SROWS * 64)                    /* 87040 */

// ---------------- device state (static, no allocation) ----------------
__device__ float d_P[NPIX*NPIX];
__device__ float d_PhiTb[BB*NPIX];
__device__ float d_x[BB*NPIX];
__device__ float d_z[BB*NPIX];
__device__ float d_gphi[BB*NPIX];
__device__ float d_dotm[BB*NPIX];
// pixel-major bf16 tensors: [image][pixel][32ch] as 16 u32 per pixel
__device__ unsigned int d_x1[BB*NPIX*16];
__device__ unsigned int d_x2[BB*NPIX*16];
__device__ unsigned int d_x3[BB*NPIX*16];
__device__ unsigned int d_g [BB*NPIX*16];
__device__ unsigned int d_bA[BB*NPIX*16];
__device__ float d_ngrad[BB];
__device__ float d_gamma;

__device__ __forceinline__ uint32_t smem_to_u32(const void* p) {
    uint32_t a;
    asm("{ .reg .u64 t; cvta.to.shared.u64 t, %1; cvt.u32.u64 %0, t; }" : "=r"(a) : "l"(p));
    return a;
}

// ---------------- bf16 pack/unpack ----------------
__device__ __forceinline__ float2 bupk(unsigned int u) {
    __nv_bfloat162 t = *reinterpret_cast<__nv_bfloat162*>(&u);
    return __bfloat1622float2(t);
}
__device__ __forceinline__ unsigned int bpk(float a, float b) {
    __nv_bfloat162 t = __floats2bfloat162_rn(a, b);
    return *reinterpret_cast<unsigned int*>(&t);
}

// ---------------- activation (eq. 33), DELTA = 0.01 ----------------
__device__ __forceinline__ float actf(float v) {
    if (fabsf(v) > 0.01f) return fmaxf(v, 0.0f);
    return fmaf(v*v, 25.0f, fmaf(v, 0.5f, 0.0025f));
}
__device__ __forceinline__ float actdf(float v) {
    if (fabsf(v) > 0.01f) return v > 0.0f ? 1.0f : 0.0f;
    return fmaf(v, 50.0f, 0.5f);
}

// ---------------- GEMM: P = Phi^T Phi ----------------
__global__ void k_phitphi64(const float* __restrict__ Phi) {
    if (blockIdx.x == 0 && blockIdx.y == 0 && threadIdx.x == 0 && threadIdx.y == 0)
        d_gamma = 1.0f;
    __shared__ float As[16][68];
    __shared__ float Bs[16][68];
    int ib = blockIdx.y * 64, jb = blockIdx.x * 64;
    int tx = threadIdx.x, ty = threadIdx.y;
    int t = ty * 16 + tx;
    float acc[4][4];
    #pragma unroll
    for (int r = 0; r < 4; r++)
        #pragma unroll
        for (int c = 0; c < 4; c++) acc[r][c] = 0.f;
    for (int k0 = 0; k0 < MDIM; k0 += 16) {
        #pragma unroll
        for (int q = t; q < 1024; q += 256) {
            int kk = q / 64, r = q % 64;
            As[kk][r] = (ib + r < NPIX) ? Phi[(k0 + kk) * NPIX + ib + r] : 0.f;
            Bs[kk][r] = (jb + r < NPIX) ? Phi[(k0 + kk) * NPIX + jb + r] : 0.f;
        }
        __syncthreads();
        #pragma unroll
        for (int kk = 0; kk < 16; kk++) {
            float4 a4 = *(const float4*)&As[kk][ty * 4];
            float4 b4 = *(const float4*)&Bs[kk][tx * 4];
            float ar[4] = {a4.x, a4.y, a4.z, a4.w};
            float br[4] = {b4.x, b4.y, b4.z, b4.w};
            #pragma unroll
            for (int r = 0; r < 4; r++)
                #pragma unroll
                for (int c = 0; c < 4; c++)
                    acc[r][c] = fmaf(ar[r], br[c], acc[r][c]);
        }
        __syncthreads();
    }
    #pragma unroll
    for (int r = 0; r < 4; r++) {
        int i = ib + ty * 4 + r;
        if (i >= NPIX) continue;
        #pragma unroll
        for (int c = 0; c < 4; c++) {
            int j = jb + tx * 4 + c;
            if (j < NPIX) d_P[i * NPIX + j] = acc[r][c];
        }
    }
}

// ---------------- phase GEMM: 32x64 tiles (144 CTAs = full wave) ----------------
__global__ void k_gemmP(const float* __restrict__ src, float* __restrict__ dst,
                        const float* __restrict__ alphas, int phase, int mode) {
    __shared__ float As[16][36];
    __shared__ float Bs[16][68];
    int bb = blockIdx.y * 32, jb = blockIdx.x * 64;
    int tx = threadIdx.x, ty = threadIdx.y;
    int t = ty * 16 + tx;
    float acc[2][4];
    #pragma unroll
    for (int r = 0; r < 2; r++)
        #pragma unroll
        for (int c = 0; c < 4; c++) acc[r][c] = 0.f;
    for (int k0 = 0; k0 < NPIX; k0 += 16) {
        #pragma unroll
        for (int q = t; q < 512; q += 256) {
            int r = q / 16, kk = q % 16;
            As[kk][r] = (k0 + kk < NPIX) ? src[(bb + r) * NPIX + k0 + kk] : 0.f;
        }
        #pragma unroll
        for (int q = t; q < 1024; q += 256) {
            int kk = q / 64, c = q % 64;
            Bs[kk][c] = (k0 + kk < NPIX && jb + c < NPIX) ? d_P[(k0 + kk) * NPIX + jb + c] : 0.f;
        }
        __syncthreads();
        #pragma unroll
        for (int kk = 0; kk < 16; kk++) {
            float a0 = As[kk][ty * 2], a1 = As[kk][ty * 2 + 1];
            float4 b4 = *(const float4*)&Bs[kk][tx * 4];
            float br[4] = {b4.x, b4.y, b4.z, b4.w};
            #pragma unroll
            for (int c = 0; c < 4; c++) {
                acc[0][c] = fmaf(a0, br[c], acc[0][c]);
                acc[1][c] = fmaf(a1, br[c], acc[1][c]);
            }
        }
        __syncthreads();
    }
    float alpha = fabsf(alphas[phase]);
    #pragma unroll
    for (int r = 0; r < 2; r++) {
        int b = bb + ty * 2 + r;
        #pragma unroll
        for (int c = 0; c < 4; c++) {
            int j = jb + tx * 4 + c;
            if (j < NPIX) {
                float dot = acc[r][c];
                float ptb = d_PhiTb[b * NPIX + j];
                if (mode == 0)
                    dst[b * NPIX + j] = src[b * NPIX + j] + alpha * (ptb - dot);
                else
                    dst[b * NPIX + j] = dot - ptb;
            }
        }
    }
}

__global__ void k_zstep(const float* __restrict__ x, float* __restrict__ z,
                        const float* __restrict__ alphas, int phase) {
    float alpha = fabsf(alphas[phase]);
    size_t base = (size_t)blockIdx.x * NPIX;
    for (int j = threadIdx.x; j < NPIX; j += blockDim.x)
        z[base + j] = x[base + j] - alpha * d_dotm[base + j];
}

__global__ void k_setupF(const float* __restrict__ Phix, const float* __restrict__ Phi,
                         const float* __restrict__ Qinit,
                         float* __restrict__ dPhiTb, float* __restrict__ dx) {
    __shared__ float As[32][33];
    __shared__ float Bs[32][33];
    int tmode = blockIdx.z;
    const float* Bsrc = tmode == 0 ? Phi : Qinit;
    float* dst = tmode == 0 ? dPhiTb : dx;
    int bb = blockIdx.y * 32, jb = blockIdx.x * 32;
    int tx = threadIdx.x, ty = threadIdx.y;
    int t = ty * 16 + tx;
    float acc00 = 0.f, acc01 = 0.f, acc10 = 0.f, acc11 = 0.f;
    for (int k0 = 0; k0 < MDIM; k0 += 32) {
        for (int q = t; q < 1024; q += 256) {
            int kk = q % 32, r = q / 32;
            As[kk][r] = (k0 + kk < MDIM) ? Phix[(bb + r) * MDIM + k0 + kk] : 0.f;
        }
        if (tmode == 0) {
            for (int q = t; q < 1024; q += 256) {
                int kk = q / 32, j = q % 32;
                Bs[kk][j] = (k0 + kk < MDIM && jb + j < NPIX) ? Bsrc[(k0 + kk) * NPIX + jb + j] : 0.f;
            }
        } else {
            for (int q = t; q < 1024; q += 256) {
                int kk = q % 32, j = q / 32;
                Bs[kk][j] = (k0 + kk < MDIM && jb + j < NPIX) ? Bsrc[(jb + j) * MDIM + k0 + kk] : 0.f;
            }
        }
        __syncthreads();
        #pragma unroll
        for (int kk = 0; kk < 32; kk++) {
            float a0 = As[kk][ty*2], a1 = As[kk][ty*2+1];
            float b0 = Bs[kk][tx*2], b1 = Bs[kk][tx*2+1];
            acc00 = fmaf(a0, b0, acc00); acc01 = fmaf(a0, b1, acc01);
            acc10 = fmaf(a1, b0, acc10); acc11 = fmaf(a1, b1, acc11);
        }
        __syncthreads();
    }
    int b0 = bb + ty*2, j0 = jb + tx*2;
    if (j0     < NPIX) dst[(b0  ) * NPIX + j0  ] = acc00;
    if (j0 + 1 < NPIX) dst[(b0  ) * NPIX + j0+1] = acc01;
    if (j0     < NPIX) dst[(b0+1) * NPIX + j0  ] = acc10;
    if (j0 + 1 < NPIX) dst[(b0+1) * NPIX + j0+1] = acc11;
}

// ---------------- tensor conv (32 -> 32) via mma.sync bf16, B in registers ---------
// FLAG_CONV1: input is z (f32); conv1 computed inline, x1 written to x1out,
// act(x1) written into the MMA row buffer.
__global__ __launch_bounds__(TC_THREADS) void k_convTC(
        const unsigned int* __restrict__ in, const float* __restrict__ w,
        unsigned int* __restrict__ out, const unsigned int* __restrict__ pre,
        const float* __restrict__ soft, int flags,
        const float* __restrict__ zin, const float* __restrict__ w1,
        unsigned int* __restrict__ x1out) {
    extern __shared__ char smem[];
    __nv_bfloat16* wt = (__nv_bfloat16*)smem;                 // [32][WT_STRIDE]
    unsigned int* srows = (unsigned int*)(smem + OFF_ROWS);   // SROWS x ROWW u32
    uint32_t rows_addr = smem_to_u32(srows);
    const int dlt[9] = {-37,-36,-35,-1,0,1,35,36,37};
    int tid = threadIdx.x;
    int lane = tid & 31, warp = tid >> 5;
    int n = blockIdx.x;

    // zero input rows
    uint4 z4 = make_uint4(0, 0, 0, 0);
    for (int i = tid; i < SROWS * 5; i += TC_THREADS) ((uint4*)srows)[i] = z4;

    // stage weights transposed: Wt[co][tap*32+ci]
    bool flip = (flags & FLAG_FLIP) != 0;
    for (int idx = tid; idx < CC * CC * 9; idx += TC_THREADS) {
        int kx = idx % 3, ky = (idx / 3) % 3;
        int i = (idx / 9) % CC, o = idx / (9 * CC);
        float v = w[idx];
        int eci, eco, ek;
        if (flip) { eci = o; eco = i; ek = (2 - ky) * 3 + (2 - kx); }
        else      { eci = i; eco = o; ek = ky * 3 + kx; }
        wt[eco * WT_STRIDE + ek * 32 + eci] = __float2bfloat16(v);
    }

    if (flags & FLAG_CONV1) {
        // ---- conv1 fused: z f32 -> x1 (gmem bf16) + act(x1) (rows) ----
        float* s_z  = (float*)(smem + OFF_SZ);
        float* s_w1 = (float*)(smem + OFF_SW1);   // [k][co]
        for (int i = tid; i < SROWS; i += TC_THREADS) s_z[i] = 0.f;
        for (int i = tid; i < 9 * CC; i += TC_THREADS) {
            int o = i / 9, k = i % 9;
            s_w1[k * CC + o] = w1[i];
        }
        __syncthreads();
        const float* zb = zin + (size_t)n * NPIX;
        for (int p = tid; p < NPIX; p += TC_THREADS) {
            int y = p / 33, x = p - y * 33;
            s_z[FRONT + (y + 1) * 36 + (x + 1)] = zb[p];
        }
        __syncthreads();
        unsigned int* xo = x1out + (size_t)n * NPIX * 16;
        for (int p = tid; p < NPIX; p += TC_THREADS) {
            int y = p / 33, x = p - y * 33;
            int pp = FRONT + (y + 1) * 36 + (x + 1);
            float zv[9];
            #pragma unroll
            for (int k = 0; k < 9; k++) zv[k] = s_z[pp + dlt[k]];
            unsigned int* row = xo + p * 16;
            unsigned int* rw = srows + pp * ROWW;
            #pragma unroll 1
            for (int ch = 0; ch < 4; ch++) {
                float acc[8];
                #pragma unroll
                for (int j = 0; j < 8; j++) acc[j] = 0.f;
                #pragma unroll
                for (int k = 0; k < 9; k++) {
                    float4 w0 = *(const float4*)(s_w1 + k * CC + ch * 8);
                    float4 w1v = *(const float4*)(s_w1 + k * CC + ch * 8 + 4);
                    acc[0] = fmaf(zv[k], w0.x, acc[0]);
                    acc[1] = fmaf(zv[k], w0.y, acc[1]);
                    acc[2] = fmaf(zv[k], w0.z, acc[2]);
                    acc[3] = fmaf(zv[k], w0.w, acc[3]);
                    acc[4] = fmaf(zv[k], w1v.x, acc[4]);
                    acc[5] = fmaf(zv[k], w1v.y, acc[5]);
                    acc[6] = fmaf(zv[k], w1v.z, acc[6]);
                    acc[7] = fmaf(zv[k], w1v.w, acc[7]);
                }
                uint4 xv = make_uint4(bpk(acc[0], acc[1]), bpk(acc[2], acc[3]),
                                      bpk(acc[4], acc[5]), bpk(acc[6], acc[7]));
                *(uint4*)(row + ch * 4) = xv;
                uint4 av = make_uint4(bpk(actf(acc[0]), actf(acc[1])),
                                      bpk(actf(acc[2]), actf(acc[3])),
                                      bpk(actf(acc[4]), actf(acc[5])),
                                      bpk(actf(acc[6]), actf(acc[7])));
                *(uint4*)(rw + ch * 4) = av;
            }
        }
    } else {
        __syncthreads();
        // stage input pixels (fused act / gnorm)
        const uint4* inb = (const uint4*)in + (size_t)n * NPIX * 4;
        bool act_in = (flags & FLAG_ACT_IN) != 0;
        bool gn = (flags & FLAG_GNORM) != 0;
        float thr = 0.f, invthr = 0.f;
        if (gn) { thr = soft[0] * d_gamma; invthr = 1.0f / thr; }
        for (int p = tid; p < NPIX; p += TC_THREADS) {
            int y = p / 33, x = p - y * 33;
            int row = FRONT + (y + 1) * 36 + (x + 1);
            uint4 q0 = inb[p*4+0], q1 = inb[p*4+1], q2 = inb[p*4+2], q3 = inb[p*4+3];
            unsigned int u[16] = {q0.x,q0.y,q0.z,q0.w, q1.x,q1.y,q1.z,q1.w,
                                  q2.x,q2.y,q2.z,q2.w, q3.x,q3.y,q3.z,q3.w};
            if (act_in) {
                #pragma unroll
                for (int j = 0; j < 16; j++) {
                    float2 f = bupk(u[j]);
                    u[j] = bpk(actf(f.x), actf(f.y));
                }
            } else if (gn) {
                float2 f[16];
                float s = 0.f;
                #pragma unroll
                for (int j = 0; j < 16; j++) {
                    f[j] = bupk(u[j]);
                    s = fmaf(f[j].x, f[j].x, fmaf(f[j].y, f[j].y, s));
                }
                float nrm = sqrtf(s);
                float fac = (nrm > thr) ? (1.0f / fmaxf(nrm, 1e-12f)) : invthr;
                #pragma unroll
                for (int j = 0; j < 16; j++)
                    u[j] = bpk(f[j].x * fac, f[j].y * fac);
            }
            uint4* dst = (uint4*)(srows + row * ROWW);
            dst[0] = make_uint4(u[0],u[1],u[2],u[3]);
            dst[1] = make_uint4(u[4],u[5],u[6],u[7]);
            dst[2] = make_uint4(u[8],u[9],u[10],u[11]);
            dst[3] = make_uint4(u[12],u[13],u[14],u[15]);
        }
    }
    __syncthreads();

    // preload ALL B fragments into registers (tile-invariant)
    uint32_t breg[KSTEPS][4][2];
    {
        int brow = lane >> 2, bcol = (lane & 3) * 2;
        #pragma unroll
        for (int s = 0; s < KSTEPS; s++) {
            #pragma unroll
            for (int nb = 0; nb < 4; nb++) {
                const __nv_bfloat16* wr = wt + (nb * 8 + brow) * WT_STRIDE + s * 16 + bcol;
                breg[s][nb][0] = *(const uint32_t*)wr;
                breg[s][nb][1] = *(const uint32_t*)(wr + 8);
            }
        }
    }

    unsigned int* outp = out + (size_t)n * NPIX * 16;
    const unsigned int* prep = pre + (size_t)n * NPIX * 16;
    bool actder = (flags & FLAG_ACTDER) != 0;

    for (int tile = warp; tile < NTILES; tile += 8) {
        int p0 = tile * 16;
        int pl = p0 + (lane & 15); if (pl > NPIX - 1) pl = NPIX - 1;
        int y = pl / 33, x = pl - y * 33;
        uint32_t abase = rows_addr
                       + (uint32_t)((FRONT + (y + 1) * 36 + (x + 1)) * 80)
                       + (uint32_t)((lane >> 4) * 16);

        float d[4][4];
        #pragma unroll
        for (int nb = 0; nb < 4; nb++)
            #pragma unroll
            for (int j = 0; j < 4; j++) d[nb][j] = 0.f;

        #pragma unroll
        for (int s = 0; s < KSTEPS; s++) {
            int t = s >> 1, h = s & 1;
            uint32_t aaddr = abase + (uint32_t)(dlt[t] * 80 + h * 32);
            uint32_t a0, a1, a2, a3;
            asm volatile("ldmatrix.sync.aligned.m8n8.x4.shared.b16 {%0,%1,%2,%3}, [%4];"
                         : "=r"(a0), "=r"(a1), "=r"(a2), "=r"(a3) : "r"(aaddr));
            #pragma unroll
            for (int nb = 0; nb < 4; nb++) {
                asm volatile(
                    "mma.sync.aligned.m16n8k16.row.col.f32.bf16.bf16.f32 "
                    "{%0,%1,%2,%3}, {%4,%5,%6,%7}, {%8,%9}, {%0,%1,%2,%3};"
                    : "+f"(d[nb][0]), "+f"(d[nb][1]), "+f"(d[nb][2]), "+f"(d[nb][3])
                    : "r"(a0), "r"(a1), "r"(a2), "r"(a3),
                      "r"(breg[s][nb][0]), "r"(breg[s][nb][1]));
            }
        }

        // epilogue: D (16x32 f32) -> pixel-major bf16 u32
        int pA = p0 + (lane >> 2);
        int pB = pA + 8;
        #pragma unroll
        for (int nb = 0; nb < 4; nb++) {
            int ci = nb * 4 + (lane & 3);     // u32 (co-pair) index within pixel
            if (pA < NPIX) {
                float c0 = d[nb][0], c1 = d[nb][1];
                if (actder) {
                    float2 f = bupk(prep[pA * 16 + ci]);
                    c0 *= actdf(f.x); c1 *= actdf(f.y);
                }
                outp[pA * 16 + ci] = bpk(c0, c1);
            }
            if (pB < NPIX) {
                float c2 = d[nb][2], c3 = d[nb][3];
                if (actder) {
                    float2 f = bupk(prep[pB * 16 + ci]);
                    c2 *= actdf(f.x); c3 *= actdf(f.y);
                }
                outp[pB * 16 + ci] = bpk(c2, c3);
            }
        }
    }
}

// ---------------- convT1 (32 -> 1) from bf16 pixel-major, fused update ----------------
__global__ __launch_bounds__(T1_THREADS) void k_convT1n(
        const unsigned int* __restrict__ in, const float* __restrict__ w1,
        const float* __restrict__ z, float* __restrict__ x,
        const float* __restrict__ dotm, float* __restrict__ gphi,
        const float* __restrict__ alphas, const float* __restrict__ betas,
        int phase, int mode, float* __restrict__ out_extra) {
    extern __shared__ char smem[];
    unsigned int* srows = (unsigned int*)smem;     // SROWS * 16 u32
    __shared__ float s_w[CC * 9];                  // flipped [o][k]
    const int dlt[9] = {-37,-36,-35,-1,0,1,35,36,37};
    int n = blockIdx.x, tid = threadIdx.x;

    uint4 z4 = make_uint4(0, 0, 0, 0);
    for (int i = tid; i < SROWS * 4; i += T1_THREADS) ((uint4*)srows)[i] = z4;
    for (int idx = tid; idx < CC * 9; idx += T1_THREADS) {
        int o = idx / 9, k = idx % 9;
        int ky = k / 3, kx = k % 3;
        s_w[o * 9 + (2 - ky) * 3 + (2 - kx)] = w1[idx];
    }
    __syncthreads();
    const uint4* inb = (const uint4*)in + (size_t)n * NPIX * 4;
    for (int p = tid; p < NPIX; p += T1_THREADS) {
        int y = p / 33, xx = p - y * 33;
        int row = FRONT + (y + 1) * 36 + (xx + 1);
        uint4* dst = (uint4*)(srows + row * 16);
        dst[0] = inb[p*4+0]; dst[1] = inb[p*4+1];
        dst[2] = inb[p*4+2]; dst[3] = inb[p*4+3];
    }
    __syncthreads();

    float a = fabsf(alphas[phase]), b = fabsf(betas[phase]);
    float tau = a * b / (a + b);

    for (int p = tid; p < NPIX; p += T1_THREADS) {
        int y = p / 33, xx = p - y * 33;
        int pp = FRONT + (y + 1) * 36 + (xx + 1);
        float acc = 0.f;
        #pragma unroll
        for (int k = 0; k < 9; k++) {
            const uint4* rp = (const uint4*)(srows + (pp + dlt[k]) * 16);
            uint4 r0 = rp[0], r1 = rp[1], r2 = rp[2], r3 = rp[3];
            unsigned int u[16] = {r0.x,r0.y,r0.z,r0.w, r1.x,r1.y,r1.z,r1.w,
                                  r2.x,r2.y,r2.z,r2.w, r3.x,r3.y,r3.z,r3.w};
            #pragma unroll
            for (int j = 0; j < 16; j++) {
                float2 f = bupk(u[j]);
                acc = fmaf(f.x, s_w[(2*j) * 9 + k], acc);
                acc = fmaf(f.y, s_w[(2*j+1) * 9 + k], acc);
            }
        }
        size_t off = (size_t)n * NPIX + p;
        if (mode == 0) {
            float nx = z[off] - tau * acc;
            x[off] = nx;
            if (out_extra) out_extra[off] = nx;
        } else {
            gphi[off] = dotm[off] + acc;
        }
    }
}

// ---------------- row norms + gamma update ----------------
__global__ void k_rownorm(const float* __restrict__ gphi) {
    __shared__ float red[256];
    int bidx = blockIdx.x;
    float s = 0.f;
    for (int j = threadIdx.x; j < NPIX; j += 256) {
        float v = gphi[(size_t)bidx * NPIX + j];
        s = fmaf(v, v, s);
    }
    red[threadIdx.x] = s;
    __syncthreads();
    for (int off = 128; off > 0; off >>= 1) {
        if (threadIdx.x < off) red[threadIdx.x] += red[threadIdx.x + off];
        __syncthreads();
    }
    if (threadIdx.x == 0) d_ngrad[bidx] = sqrtf(red[0]);
}

__global__ void k_gamma(const float* __restrict__ soft_thr) {
    __shared__ float red[256];
    red[threadIdx.x] = d_ngrad[threadIdx.x];
    __syncthreads();
    for (int off = 128; off > 0; off >>= 1) {
        if (threadIdx.x < off) red[threadIdx.x] += red[threadIdx.x + off];
        __syncthreads();
    }
    if (threadIdx.x == 0) {
        float mean = red[0] / (float)BB;
        float g = d_gamma;
        if (mean < 15000.0f * g * soft_thr[0]) g *= 0.9f;
        d_gamma = g;
    }
}

// ---------------- host orchestration ----------------
static void grad_r_chain(const float* src, const float* c1, const float* c2,
                         const float* c3, const float* c4, const float* soft,
                         unsigned int* px1, unsigned int* px2, unsigned int* px3,
                         unsigned int* pg, unsigned int* pbA,
                         const float* pz, float* px, const float* pdotm, float* pgphi,
                         const float* alphas, const float* betas,
                         int phase, int mode, float* out_extra) {
    // conv1 fused into the first tensor conv
    k_convTC<<<BB, TC_THREADS, SMEM_TC2>>>(px1, c2, px2, px1, soft, FLAG_CONV1,
                                           src, c1, px1);
    k_convTC<<<BB, TC_THREADS, SMEM_TC>>>(px2, c3, px3, px1, soft, FLAG_ACT_IN,
                                          nullptr, nullptr, nullptr);
    k_convTC<<<BB, TC_THREADS, SMEM_TC>>>(px3, c4, pg,  px1, soft, FLAG_ACT_IN,
                                          nullptr, nullptr, nullptr);
    k_convTC<<<BB, TC_THREADS, SMEM_TC>>>(pg,  c4, pbA, px3, soft,
                                          FLAG_FLIP | FLAG_ACTDER | FLAG_GNORM,
                                          nullptr, nullptr, nullptr);
    k_convTC<<<BB, TC_THREADS, SMEM_TC>>>(pbA, c3, pg,  px2, soft,
                                          FLAG_FLIP | FLAG_ACTDER,
                                          nullptr, nullptr, nullptr);
    k_convTC<<<BB, TC_THREADS, SMEM_TC>>>(pg,  c2, pbA, px1, soft,
                                          FLAG_FLIP | FLAG_ACTDER,
                                          nullptr, nullptr, nullptr);
    k_convT1n<<<BB, T1_THREADS, SMEM_T1N>>>(pbA, c1, pz, px, pdotm, pgphi,
                                            alphas, betas, phase, mode, out_extra);
}

extern "C" void kernel_launch(void* const* d_in, const int* in_sizes, int n_in,
                              void* d_out, int out_size) {
    (void)in_sizes; (void)n_in; (void)out_size;
    const float* Phix   = (const float*)d_in[0];
    const float* Phi    = (const float*)d_in[1];
    const float* Qinit  = (const float*)d_in[2];
    const float* soft   = (const float*)d_in[3];
    const float* alphas = (const float*)d_in[4];
    const float* betas  = (const float*)d_in[5];
    const float* c1     = (const float*)d_in[6];
    const float* c2     = (const float*)d_in[7];
    const float* c3     = (const float*)d_in[8];
    const float* c4     = (const float*)d_in[9];
    float* out = (float*)d_out;

    cudaFuncSetAttribute(k_convTC,  cudaFuncAttributeMaxDynamicSharedMemorySize, SMEM_TC2);
    cudaFuncSetAttribute(k_convT1n, cudaFuncAttributeMaxDynamicSharedMemorySize, SMEM_T1N);

    float *px, *pz, *pgphi, *pdotm, *pPhiTb;
    unsigned int *px1, *px2, *px3, *pg, *pbA;
    cudaGetSymbolAddress((void**)&px,     d_x);
    cudaGetSymbolAddress((void**)&pz,     d_z);
    cudaGetSymbolAddress((void**)&pgphi,  d_gphi);
    cudaGetSymbolAddress((void**)&pdotm,  d_dotm);
    cudaGetSymbolAddress((void**)&px1,    d_x1);
    cudaGetSymbolAddress((void**)&px2,    d_x2);
    cudaGetSymbolAddress((void**)&px3,    d_x3);
    cudaGetSymbolAddress((void**)&pg,     d_g);
    cudaGetSymbolAddress((void**)&pbA,    d_bA);
    cudaGetSymbolAddress((void**)&pPhiTb, d_PhiTb);

    dim3 tb16(16, 16);
    k_phitphi64<<<dim3(18, 18), tb16>>>(Phi);                       // + gamma init
    k_setupF<<<dim3(35, 8, 2), tb16>>>(Phix, Phi, Qinit, pPhiTb, px);

    for (int p = 0; p < 3; p++) {
        if (p == 0)
            k_gemmP<<<dim3(18, 8), tb16>>>(px, pz, alphas, p, 0);
        else
            k_zstep<<<BB, 256>>>(px, pz, alphas, p);
        grad_r_chain(pz, c1, c2, c3, c4, soft, px1, px2, px3, pg, pbA,
                     pz, px, pdotm, pgphi, alphas, betas, p, 0,
                     (p == 2) ? out : nullptr);
        if (p < 2) {
            k_gemmP<<<dim3(18, 8), tb16>>>(px, pdotm, alphas, p, 1);
            grad_r_chain(px, c1, c2, c3, c4, soft, px1, px2, px3, pg, pbA,
                         pz, px, pdotm, pgphi, alphas, betas, p, 1, nullptr);
            k_rownorm<<<BB, 256>>>(pgphi);
            k_gamma<<<1, 256>>>(soft);
        }
    }
}